// round 13
// baseline (speedup 1.0000x reference)
#include <cuda_runtime.h>
#include <cuda_fp16.h>
#include <cstdint>

// ---------------------------------------------------------------------------
// Problem constants: B=2, L=2048, D=1024, H=16, hd=64
// ---------------------------------------------------------------------------
#define BATCH 2
#define SEQ   2048
#define DMODEL 1024
#define NHEAD 16
#define HDIM  64
#define MTOT  (BATCH * SEQ)          // 4096
#define CEXPF 0.1803368801111f       // 0.125 * log2(e), folded into q
#define DW32  (DMODEL / 2)           // 512 uint32 (half2) per row

// Scratch (device globals). All fp16 operands stored half2-packed as uint32.
__device__ uint32_t g_xr[MTOT * DW32];
__device__ uint32_t g_wq[DMODEL * DW32];
__device__ uint32_t g_wk[DMODEL * DW32];
__device__ uint32_t g_wv[DMODEL * DW32];
__device__ uint32_t g_wo[DMODEL * DW32];
__device__ uint32_t g_q[MTOT * DMODEL / 2];    // [b*16+h][l][32 u32]
__device__ uint32_t g_k[MTOT * DMODEL / 2];
__device__ uint16_t g_vt[MTOT * DMODEL];       // [b*16+h][hd][l] halves
__device__ uint32_t g_ctx[MTOT * DW32];        // [b*SEQ+l][512 u32]

__device__ __forceinline__ float ex2(float x) {
    float r;
    asm("ex2.approx.f32 %0, %1;" : "=f"(r) : "f"(x));
    return r;
}
__device__ __forceinline__ uint32_t smem_u32(const void* p) {
    uint32_t a;
    asm("{ .reg .u64 t; cvta.to.shared.u64 t, %1; cvt.u32.u64 %0, t; }" : "=r"(a) : "l"(p));
    return a;
}
__device__ __forceinline__ void cp16(uint32_t smem, const void* g) {
    asm volatile("cp.async.cg.shared.global [%0], [%1], 16;"
                 :: "r"(smem), "l"(__cvta_generic_to_global(g)));
}
__device__ __forceinline__ void mma_f16(float* d, const uint32_t* a, const uint32_t* b) {
    asm volatile(
        "mma.sync.aligned.m16n8k16.row.col.f32.f16.f16.f32 "
        "{%0,%1,%2,%3}, {%4,%5,%6,%7}, {%8,%9}, {%0,%1,%2,%3};\n"
        : "+f"(d[0]), "+f"(d[1]), "+f"(d[2]), "+f"(d[3])
        : "r"(a[0]), "r"(a[1]), "r"(a[2]), "r"(a[3]), "r"(b[0]), "r"(b[1]));
}
__device__ __forceinline__ void ldsm4(uint32_t& r0, uint32_t& r1, uint32_t& r2,
                                      uint32_t& r3, uint32_t a) {
    asm volatile("ldmatrix.sync.aligned.m8n8.x4.shared.b16 {%0,%1,%2,%3}, [%4];"
                 : "=r"(r0), "=r"(r1), "=r"(r2), "=r"(r3) : "r"(a));
}
__device__ __forceinline__ uint32_t h2bits(float a, float b) {
    __half2 h = __floats2half2_rn(a, b);
    return *reinterpret_cast<uint32_t*>(&h);
}
__device__ __forceinline__ uint16_t hbits(float a) {
    __half h = __float2half_rn(a);
    return *reinterpret_cast<uint16_t*>(&h);
}

// ---------------------------------------------------------------------------
// Fused fp16 round+pack of x and all 4 weights (one launch).
// ---------------------------------------------------------------------------
#define X4 (MTOT * DMODEL / 4)
#define W4 (DMODEL * DMODEL / 4)
#define TOTAL4 (X4 + 4 * W4)

__global__ __launch_bounds__(256) void round_pack(
    const float* __restrict__ x, const float* __restrict__ Wq,
    const float* __restrict__ Wk, const float* __restrict__ Wv,
    const float* __restrict__ Wo) {
    const int idx = blockIdx.x * 256 + threadIdx.x;
    if (idx >= TOTAL4) return;
    const float* src;
    uint2* dst;
    int li;
    if (idx < X4) {
        src = x; dst = reinterpret_cast<uint2*>(g_xr); li = idx;
    } else {
        const int r = idx - X4;
        const int w = r >> 18;
        li = r & (W4 - 1);
        switch (w) {
            case 0: src = Wq; dst = reinterpret_cast<uint2*>(g_wq); break;
            case 1: src = Wk; dst = reinterpret_cast<uint2*>(g_wk); break;
            case 2: src = Wv; dst = reinterpret_cast<uint2*>(g_wv); break;
            default: src = Wo; dst = reinterpret_cast<uint2*>(g_wo); break;
        }
    }
    float4 v = reinterpret_cast<const float4*>(src)[li];
    dst[li] = make_uint2(h2bits(v.x, v.y), h2bits(v.z, v.w));
}

// ---------------------------------------------------------------------------
// FP16 mma.sync GEMM: C = A @ B^T over half2-packed inputs.
// 4-CTA/SM CONFIG (R12-proven): CTA 128x64, 128 threads = 4 warps (2m x 2n),
// warp 64x32, 2-stage cp.async, frag double-buffer.
// NEW: V epilogue stages the transpose through smem -> coalesced u32 stores.
// MODE 1 (QKV fused, N=3072); MODE 0 (Wo).
// ---------------------------------------------------------------------------
#define GSTR 36
#define GASTG (128 * GSTR)                   // A u32 per stage
#define GBSTG (64 * GSTR)                    // B u32 per stage
#define GSMEM_BYTES (2 * (GASTG + GBSTG) * 4)  // 55296 B
#define GNCHUNK 16
#define VT_STR 132                           // halves stride for V transpose

template <int MODE>
__global__ __launch_bounds__(128, 4) void gemm_mma(const uint32_t* __restrict__ A,
                                                   const uint32_t* __restrict__ B0,
                                                   const uint32_t* __restrict__ B1,
                                                   const uint32_t* __restrict__ B2,
                                                   float* __restrict__ Cf,
                                                   uint32_t* __restrict__ Cq,
                                                   uint32_t* __restrict__ Ck,
                                                   uint16_t* __restrict__ Cvt) {
    extern __shared__ uint32_t sm32[];
    const uint32_t as_a = smem_u32(sm32);
    const uint32_t bs_a = as_a + 2 * GASTG * 4;

    const int tid = threadIdx.x;
    const int bm = blockIdx.y * 128;
    const int bnab = blockIdx.x * 64;

    const uint32_t* B = B0;
    int bn = bnab;
    if (MODE == 1) {
        if (bnab >= 2048)      B = B2;
        else if (bnab >= 1024) B = B1;
        bn = bnab & 1023;
    }

    const int wid = tid >> 5;
    const int lane = tid & 31;
    const int wm = (wid >> 1) * 64;      // 2 m-warps
    const int wn = (wid & 1) * 32;       // 2 n-warps
    const int gid = lane >> 2;
    const int tig = lane & 3;

    // LDSM lane->address mapping (u32 units within a tile row)
    const int a_lrow = (lane & 7) + ((lane >> 3) & 1) * 8;
    const int a_lcol = (lane >> 4) * 4;
    const int b_lrow = (lane & 7) + (lane >> 4) * 8;
    const int b_lcol = ((lane >> 3) & 1) * 4;

    auto issue_chunk = [&](int c, int buf) {
        const uint32_t ab = as_a + (uint32_t)buf * GASTG * 4;
        const uint32_t bb = bs_a + (uint32_t)buf * GBSTG * 4;
        const int k0 = c * 32;
#pragma unroll
        for (int u = 0; u < 8; u++) {
            const int idx = u * 128 + tid;
            const int r = idx >> 3;
            const int ch = idx & 7;
            cp16(ab + (uint32_t)(r * GSTR + ch * 4) * 4,
                 A + (size_t)(bm + r) * DW32 + k0 + ch * 4);
        }
#pragma unroll
        for (int u = 0; u < 4; u++) {
            const int idx = u * 128 + tid;
            const int r = idx >> 3;
            const int ch = idx & 7;
            cp16(bb + (uint32_t)(r * GSTR + ch * 4) * 4,
                 B + (size_t)(bn + r) * DW32 + k0 + ch * 4);
        }
    };

    float acc[4][4][4];
#pragma unroll
    for (int i = 0; i < 4; i++)
#pragma unroll
        for (int j = 0; j < 4; j++)
#pragma unroll
            for (int r = 0; r < 4; r++) acc[i][j][r] = 0.0f;

    issue_chunk(0, 0);
    asm volatile("cp.async.commit_group;");
    issue_chunk(1, 1);
    asm volatile("cp.async.commit_group;");

    for (int c = 0; c < GNCHUNK; c++) {
        asm volatile("cp.async.wait_group 1;");
        __syncthreads();

        const int buf = c & 1;
        const uint32_t aaddr = as_a + (uint32_t)buf * GASTG * 4 +
                               (uint32_t)(((wm + a_lrow) * GSTR) + a_lcol) * 4;
        const uint32_t baddr = bs_a + (uint32_t)buf * GBSTG * 4 +
                               (uint32_t)(((wn + b_lrow) * GSTR) + b_lcol) * 4;

        uint32_t af[2][4][4], bf[2][4][2];

        auto load_frags = [&](int kk, int d) {
#pragma unroll
            for (int mt = 0; mt < 4; mt++)
                ldsm4(af[d][mt][0], af[d][mt][1], af[d][mt][2], af[d][mt][3],
                      aaddr + (uint32_t)(mt * 16 * GSTR + kk) * 4);
#pragma unroll
            for (int u = 0; u < 2; u++)
                ldsm4(bf[d][2 * u][0], bf[d][2 * u][1],
                      bf[d][2 * u + 1][0], bf[d][2 * u + 1][1],
                      baddr + (uint32_t)(u * 16 * GSTR + kk) * 4);
        };

        load_frags(0, 0);
#pragma unroll
        for (int ks = 0; ks < 4; ks++) {
            const int cur = ks & 1;
            if (ks < 3) load_frags((ks + 1) * 8, cur ^ 1);
#pragma unroll
            for (int mt = 0; mt < 4; mt++)
#pragma unroll
                for (int nt = 0; nt < 4; nt++)
                    mma_f16(acc[mt][nt], af[cur][mt], bf[cur][nt]);
        }
        __syncthreads();

        if (c + 2 < GNCHUNK) issue_chunk(c + 2, buf);
        asm volatile("cp.async.commit_group;");
    }

    const bool is_q = (MODE == 1) && (bnab < 1024);
    const bool is_v = (MODE == 1) && (bnab >= 2048);

    if (is_v) {
        // ---- V epilogue: transpose via smem, coalesced u32 stores along l ----
        __syncthreads();   // all warps done with pipeline smem (all groups drained)
        uint16_t* svh = reinterpret_cast<uint16_t*>(sm32);
#pragma unroll
        for (int mt = 0; mt < 4; mt++) {
#pragma unroll
            for (int nt = 0; nt < 4; nt++) {
                const int col = wn + nt * 8 + 2 * tig;   // dd local (even)
#pragma unroll
                for (int half = 0; half < 2; half++) {
                    const int row = wm + mt * 16 + gid + 8 * half;  // l local
                    svh[(col)     * VT_STR + row] = hbits(acc[mt][nt][2 * half]);
                    svh[(col + 1) * VT_STR + row] = hbits(acc[mt][nt][2 * half + 1]);
                }
            }
        }
        __syncthreads();
        const int b = bm >> 11;
        const int bl = bm & (SEQ - 1);
        const int h = bn >> 6;
        const int bh = b * NHEAD + h;
        uint32_t* Cvt32 = reinterpret_cast<uint32_t*>(Cvt);
#pragma unroll
        for (int u = 0; u < 32; u++) {
            const int idx = u * 128 + tid;
            const int dd = idx >> 6;           // 0..63
            const int lc = idx & 63;           // u32 index along l
            const uint32_t val =
                *reinterpret_cast<const uint32_t*>(&svh[dd * VT_STR + 2 * lc]);
            Cvt32[(((size_t)bh * HDIM + dd) * SEQ + bl + 2 * lc) >> 1] = val;
        }
        return;
    }

#pragma unroll
    for (int mt = 0; mt < 4; mt++) {
        const int row0 = bm + wm + mt * 16 + gid;
#pragma unroll
        for (int nt = 0; nt < 4; nt++) {
            const int gcol = bn + wn + nt * 8 + 2 * tig;
#pragma unroll
            for (int half = 0; half < 2; half++) {
                const int row = row0 + 8 * half;
                float v0 = acc[mt][nt][2 * half];
                float v1 = acc[mt][nt][2 * half + 1];
                if (MODE == 0) {
                    *reinterpret_cast<float2*>(Cf + (size_t)row * DMODEL + gcol) =
                        make_float2(v0, v1);
                } else {
                    const int b = row >> 11;
                    const int l = row & (SEQ - 1);
                    const int h = gcol >> 6;
                    const int dd = gcol & (HDIM - 1);
                    const int bh = b * NHEAD + h;
                    if (is_q) { v0 *= CEXPF; v1 *= CEXPF; }
                    uint32_t* dst = (is_q ? Cq : Ck);
                    dst[((size_t)bh * SEQ + l) * 32 + (dd >> 1)] = h2bits(v0, v1);
                }
            }
        }
    }
}

// ---------------------------------------------------------------------------
// Flash attention, fp16 mma.sync m16n8k16, causal.  (R12 base + skip of
// fully-masked warp-blocks on the diagonal; warp-uniform, barrier-free region)
// ---------------------------------------------------------------------------
#define FA_BK 64
#define FA_STR 36
#define FA_ST (64 * FA_STR)
#define FA_SMEM_BYTES (6 * FA_ST * 4)   // 55296 B

__device__ __forceinline__ void fa_load_kv(uint32_t ks_a, uint32_t vs_a,
                                           const uint32_t* Kg, const uint16_t* Vtg,
                                           int k0, int stage, int tid) {
    const uint32_t ko = ks_a + (uint32_t)stage * (FA_ST * 4);
    const uint32_t vo = vs_a + (uint32_t)stage * (FA_ST * 4);
#pragma unroll
    for (int u = 0; u < 2; u++) {
        const int idx = u * 256 + tid;
        const int r = idx >> 3;
        const int ch = idx & 7;
        cp16(ko + (uint32_t)(r * FA_STR + ch * 4) * 4,
             Kg + (size_t)(k0 + r) * 32 + ch * 4);
        cp16(vo + (uint32_t)(r * FA_STR + ch * 4) * 4,
             Vtg + (size_t)r * SEQ + k0 + ch * 8);
    }
}

__global__ __launch_bounds__(256, 2) void flash_mma(const uint32_t* __restrict__ Q,
                                                    const uint32_t* __restrict__ K,
                                                    const uint16_t* __restrict__ Vt,
                                                    uint32_t* __restrict__ ctx) {
    extern __shared__ uint32_t fs32[];
    uint32_t* Ks = fs32;
    uint32_t* Vs = fs32 + 3 * FA_ST;

    const int tid = threadIdx.x;
    const int w = tid >> 5;
    const int lane = tid & 31;
    const int gid = lane >> 2;
    const int tig = lane & 3;
    const int bh = blockIdx.y;
    const int qb = (int)gridDim.x - 1 - (int)blockIdx.x;
    const int q0 = qb * 128;

    const int b_lrow = (lane & 7) + (lane >> 4) * 8;
    const int b_lcol = ((lane >> 3) & 1) * 4;

    const uint32_t* Qg = Q + ((size_t)bh * SEQ + q0) * 32;
    const uint32_t* Kg = K + (size_t)bh * SEQ * 32;
    const uint16_t* Vtg = Vt + (size_t)bh * HDIM * SEQ;

    const uint32_t ks_a = smem_u32(Ks);
    const uint32_t vs_a = smem_u32(Vs);

    const int nkb = 2 * qb + 2;
    const int rq = 16 * w + gid;

    fa_load_kv(ks_a, vs_a, Kg, Vtg, 0, 0, tid);
    asm volatile("cp.async.commit_group;");
    if (nkb > 1) fa_load_kv(ks_a, vs_a, Kg, Vtg, FA_BK, 1, tid);
    asm volatile("cp.async.commit_group;");

    uint32_t qa_all[4][4];
#pragma unroll
    for (int g = 0; g < 4; g++) {
        qa_all[g][0] = Qg[(size_t)rq * 32 + 8 * g + tig];
        qa_all[g][1] = Qg[(size_t)(rq + 8) * 32 + 8 * g + tig];
        qa_all[g][2] = Qg[(size_t)rq * 32 + 8 * g + tig + 4];
        qa_all[g][3] = Qg[(size_t)(rq + 8) * 32 + 8 * g + tig + 4];
    }

    float o[8][4];
#pragma unroll
    for (int nt = 0; nt < 8; nt++)
#pragma unroll
        for (int e = 0; e < 4; e++) o[nt][e] = 0.0f;
    float m0 = -1e30f, m1 = -1e30f, l0 = 0.0f, l1 = 0.0f;

    for (int kb = 0; kb < nkb; kb++) {
        asm volatile("cp.async.wait_group 1;");
        __syncthreads();
        if (kb + 2 < nkb) fa_load_kv(ks_a, vs_a, Kg, Vtg, (kb + 2) * FA_BK, (kb + 2) % 3, tid);
        asm volatile("cp.async.commit_group;");

        const int k0 = kb * FA_BK;
        // Fully-masked warp-block (diagonal overhang): contributes nothing.
        // Condition is warp-uniform and the region below has no barriers.
        if (k0 > q0 + 16 * w + 15) continue;

        const int buf = kb % 3;
        const uint32_t kaddr = ks_a + (uint32_t)buf * FA_ST * 4 +
                               (uint32_t)(b_lrow * FA_STR + b_lcol) * 4;
        const uint32_t vaddr = vs_a + (uint32_t)buf * FA_ST * 4 +
                               (uint32_t)(b_lrow * FA_STR + b_lcol) * 4;

        float c[8][4];
#pragma unroll
        for (int nt = 0; nt < 8; nt++)
#pragma unroll
            for (int e = 0; e < 4; e++) c[nt][e] = 0.0f;

#pragma unroll
        for (int g = 0; g < 4; g++) {
            uint32_t kf[8][2];
#pragma unroll
            for (int u = 0; u < 4; u++)
                ldsm4(kf[2 * u][0], kf[2 * u][1], kf[2 * u + 1][0], kf[2 * u + 1][1],
                      kaddr + (uint32_t)(u * 16 * FA_STR + 8 * g) * 4);
#pragma unroll
            for (int nt = 0; nt < 8; nt++) mma_f16(c[nt], qa_all[g], kf[nt]);
        }

        if (k0 + 63 > q0 + 16 * w) {
            const int r0g = q0 + rq;
#pragma unroll
            for (int nt = 0; nt < 8; nt++) {
                const int cb = k0 + 8 * nt + 2 * tig;
                if (cb > r0g) c[nt][0] = -1e30f;
                if (cb + 1 > r0g) c[nt][1] = -1e30f;
                if (cb > r0g + 8) c[nt][2] = -1e30f;
                if (cb + 1 > r0g + 8) c[nt][3] = -1e30f;
            }
        }

        float mx0 = -1e30f, mx1 = -1e30f;
#pragma unroll
        for (int nt = 0; nt < 8; nt++) {
            mx0 = fmaxf(mx0, fmaxf(c[nt][0], c[nt][1]));
            mx1 = fmaxf(mx1, fmaxf(c[nt][2], c[nt][3]));
        }
        mx0 = fmaxf(mx0, __shfl_xor_sync(0xffffffffu, mx0, 1));
        mx0 = fmaxf(mx0, __shfl_xor_sync(0xffffffffu, mx0, 2));
        mx1 = fmaxf(mx1, __shfl_xor_sync(0xffffffffu, mx1, 1));
        mx1 = fmaxf(mx1, __shfl_xor_sync(0xffffffffu, mx1, 2));

        const float mn0 = fmaxf(fmaxf(m0, mx0), -1000.0f);
        const float mn1 = fmaxf(fmaxf(m1, mx1), -1000.0f);
        const float corr0 = ex2(m0 - mn0);
        const float corr1 = ex2(m1 - mn1);

        float rs0 = 0.0f, rs1 = 0.0f;
        uint32_t pw[8][2];
#pragma unroll
        for (int nt = 0; nt < 8; nt++) {
            const float p0 = ex2(c[nt][0] - mn0);
            const float p1 = ex2(c[nt][1] - mn0);
            const float p2 = ex2(c[nt][2] - mn1);
            const float p3 = ex2(c[nt][3] - mn1);
            rs0 += p0 + p1;
            rs1 += p2 + p3;
            pw[nt][0] = h2bits(p0, p1);
            pw[nt][1] = h2bits(p2, p3);
        }

#pragma unroll
        for (int nt = 0; nt < 8; nt++) {
            o[nt][0] *= corr0;
            o[nt][1] *= corr0;
            o[nt][2] *= corr1;
            o[nt][3] *= corr1;
        }

        // --- O += P V (PV burst first; l-bookkeeping deferred below) ---
#pragma unroll
        for (int j = 0; j < 4; j++) {
            uint32_t pa[4] = {pw[2 * j][0], pw[2 * j][1],
                              pw[2 * j + 1][0], pw[2 * j + 1][1]};
            uint32_t vf[8][2];
#pragma unroll
            for (int u = 0; u < 4; u++)
                ldsm4(vf[2 * u][0], vf[2 * u][1], vf[2 * u + 1][0], vf[2 * u + 1][1],
                      vaddr + (uint32_t)(u * 16 * FA_STR + 8 * j) * 4);
#pragma unroll
            for (int nt = 0; nt < 8; nt++) mma_f16(o[nt], pa, vf[nt]);
        }

        // deferred: rs reduction + l/m update (independent of o-path)
        rs0 += __shfl_xor_sync(0xffffffffu, rs0, 1);
        rs0 += __shfl_xor_sync(0xffffffffu, rs0, 2);
        rs1 += __shfl_xor_sync(0xffffffffu, rs1, 1);
        rs1 += __shfl_xor_sync(0xffffffffu, rs1, 2);
        l0 = l0 * corr0 + rs0;
        l1 = l1 * corr1 + rs1;
        m0 = mn0;
        m1 = mn1;
    }

    const float inv0 = 1.0f / l0;
    const float inv1 = 1.0f / l1;
    const int b = bh >> 4;
    const int h = bh & 15;
    const int r0 = q0 + rq;
#pragma unroll
    for (int nt = 0; nt < 8; nt++) {
        const int ci = h * 32 + 4 * nt + tig;
        ctx[((size_t)(b * SEQ + r0)) * DW32 + ci] = h2bits(o[nt][0] * inv0, o[nt][1] * inv0);
        ctx[((size_t)(b * SEQ + r0 + 8)) * DW32 + ci] = h2bits(o[nt][2] * inv1, o[nt][3] * inv1);
    }
}

// ---------------------------------------------------------------------------
// Launch
// ---------------------------------------------------------------------------
template <typename T>
static T* sym_addr(const void* symbol) {
    void* p = nullptr;
    cudaGetSymbolAddress(&p, symbol);
    return reinterpret_cast<T*>(p);
}

extern "C" void kernel_launch(void* const* d_in, const int* in_sizes, int n_in,
                              void* d_out, int out_size) {
    const float* x  = (const float*)d_in[0];
    const float* Wq = (const float*)d_in[1];
    const float* Wk = (const float*)d_in[2];
    const float* Wv = (const float*)d_in[3];
    const float* Wo = (const float*)d_in[4];
    float* out = (float*)d_out;

    uint32_t* xr = sym_addr<uint32_t>(g_xr);
    uint32_t* wq = sym_addr<uint32_t>(g_wq);
    uint32_t* wk = sym_addr<uint32_t>(g_wk);
    uint32_t* wv = sym_addr<uint32_t>(g_wv);
    uint32_t* wo = sym_addr<uint32_t>(g_wo);
    uint32_t* q  = sym_addr<uint32_t>(g_q);
    uint32_t* k  = sym_addr<uint32_t>(g_k);
    uint16_t* vt = sym_addr<uint16_t>(g_vt);
    uint32_t* ctx = sym_addr<uint32_t>(g_ctx);

    cudaFuncSetAttribute(gemm_mma<1>, cudaFuncAttributeMaxDynamicSharedMemorySize, GSMEM_BYTES);
    cudaFuncSetAttribute(gemm_mma<0>, cudaFuncAttributeMaxDynamicSharedMemorySize, GSMEM_BYTES);
    cudaFuncSetAttribute(flash_mma, cudaFuncAttributeMaxDynamicSharedMemorySize, FA_SMEM_BYTES);

    round_pack<<<(TOTAL4 + 255) / 256, 256>>>(x, Wq, Wk, Wv, Wo);

    dim3 gqkv(3 * DMODEL / 64, MTOT / 128);    // (48, 32) = 1536 CTAs
    gemm_mma<1><<<gqkv, 128, GSMEM_BYTES>>>(xr, wq, wk, wv, nullptr, q, k, vt);

    dim3 ga(SEQ / 128, BATCH * NHEAD);         // (16, 32)
    flash_mma<<<ga, 256, FA_SMEM_BYTES>>>(q, k, vt, ctx);

    dim3 go(DMODEL / 64, MTOT / 128);          // (16, 32) = 512 CTAs
    gemm_mma<0><<<go, 128, GSMEM_BYTES>>>(ctx, wo, nullptr, nullptr, out, nullptr, nullptr, nullptr);
}

// round 14
// speedup vs baseline: 1.0336x; 1.0336x over previous
#include <cuda_runtime.h>
#include <cuda_fp16.h>
#include <cstdint>

// ---------------------------------------------------------------------------
// Problem constants: B=2, L=2048, D=1024, H=16, hd=64
// ---------------------------------------------------------------------------
#define BATCH 2
#define SEQ   2048
#define DMODEL 1024
#define NHEAD 16
#define HDIM  64
#define MTOT  (BATCH * SEQ)          // 4096
#define CEXPF 0.1803368801111f       // 0.125 * log2(e), folded into q
#define DW32  (DMODEL / 2)           // 512 uint32 (half2) per row

// Scratch (device globals). All fp16 operands stored half2-packed as uint32.
__device__ uint32_t g_xr[MTOT * DW32];
__device__ uint32_t g_wq[DMODEL * DW32];
__device__ uint32_t g_wk[DMODEL * DW32];
__device__ uint32_t g_wv[DMODEL * DW32];
__device__ uint32_t g_wo[DMODEL * DW32];
__device__ uint32_t g_q[MTOT * DMODEL / 2];    // [b*16+h][l][32 u32]
__device__ uint32_t g_k[MTOT * DMODEL / 2];
__device__ uint16_t g_vt[MTOT * DMODEL];       // [b*16+h][hd][l] halves
__device__ uint32_t g_ctx[MTOT * DW32];        // [b*SEQ+l][512 u32]

__device__ __forceinline__ float ex2(float x) {
    float r;
    asm("ex2.approx.f32 %0, %1;" : "=f"(r) : "f"(x));
    return r;
}
__device__ __forceinline__ uint32_t smem_u32(const void* p) {
    uint32_t a;
    asm("{ .reg .u64 t; cvta.to.shared.u64 t, %1; cvt.u32.u64 %0, t; }" : "=r"(a) : "l"(p));
    return a;
}
__device__ __forceinline__ void cp16(uint32_t smem, const void* g) {
    asm volatile("cp.async.cg.shared.global [%0], [%1], 16;"
                 :: "r"(smem), "l"(__cvta_generic_to_global(g)));
}
__device__ __forceinline__ void mma_f16(float* d, const uint32_t* a, const uint32_t* b) {
    asm volatile(
        "mma.sync.aligned.m16n8k16.row.col.f32.f16.f16.f32 "
        "{%0,%1,%2,%3}, {%4,%5,%6,%7}, {%8,%9}, {%0,%1,%2,%3};\n"
        : "+f"(d[0]), "+f"(d[1]), "+f"(d[2]), "+f"(d[3])
        : "r"(a[0]), "r"(a[1]), "r"(a[2]), "r"(a[3]), "r"(b[0]), "r"(b[1]));
}
__device__ __forceinline__ void ldsm4(uint32_t& r0, uint32_t& r1, uint32_t& r2,
                                      uint32_t& r3, uint32_t a) {
    asm volatile("ldmatrix.sync.aligned.m8n8.x4.shared.b16 {%0,%1,%2,%3}, [%4];"
                 : "=r"(r0), "=r"(r1), "=r"(r2), "=r"(r3) : "r"(a));
}
__device__ __forceinline__ uint32_t h2bits(float a, float b) {
    __half2 h = __floats2half2_rn(a, b);
    return *reinterpret_cast<uint32_t*>(&h);
}
__device__ __forceinline__ uint16_t hbits(float a) {
    __half h = __float2half_rn(a);
    return *reinterpret_cast<uint16_t*>(&h);
}

// ---- mbarrier helpers (plain sm_100 PTX, no 'a' features) ----
#define MBAR_INIT(addr, cnt) \
    asm volatile("mbarrier.init.shared.b64 [%0], %1;" :: "r"(addr), "r"((uint32_t)(cnt)) : "memory")
#define MBAR_ARRIVE(addr) \
    asm volatile("mbarrier.arrive.shared.b64 _, [%0];" :: "r"(addr) : "memory")
#define CP_ARRIVE_NOINC(addr) \
    asm volatile("cp.async.mbarrier.arrive.noinc.shared::cta.b64 [%0];" :: "r"(addr) : "memory")

__device__ __forceinline__ void mbar_wait_parity(uint32_t mbar, uint32_t parity) {
    uint32_t done;
    asm volatile(
        "{\n\t.reg .pred p;\n\t"
        "mbarrier.try_wait.parity.shared.b64 p, [%1], %2;\n\t"
        "selp.b32 %0, 1, 0, p;\n\t}"
        : "=r"(done) : "r"(mbar), "r"(parity) : "memory");
    if (!done) {
        asm volatile(
            "{\n\t.reg .pred P1;\n\t"
            "W_%=:\n\t"
            "mbarrier.try_wait.parity.shared.b64 P1, [%0], %1;\n\t"
            "@P1 bra.uni D_%=;\n\t"
            "bra.uni W_%=;\n\t"
            "D_%=:\n\t}"
            :: "r"(mbar), "r"(parity) : "memory");
    }
}

// ---------------------------------------------------------------------------
// Fused fp16 round+pack of x and all 4 weights (one launch).
// ---------------------------------------------------------------------------
#define X4 (MTOT * DMODEL / 4)
#define W4 (DMODEL * DMODEL / 4)
#define TOTAL4 (X4 + 4 * W4)

__global__ __launch_bounds__(256) void round_pack(
    const float* __restrict__ x, const float* __restrict__ Wq,
    const float* __restrict__ Wk, const float* __restrict__ Wv,
    const float* __restrict__ Wo) {
    const int idx = blockIdx.x * 256 + threadIdx.x;
    if (idx >= TOTAL4) return;
    const float* src;
    uint2* dst;
    int li;
    if (idx < X4) {
        src = x; dst = reinterpret_cast<uint2*>(g_xr); li = idx;
    } else {
        const int r = idx - X4;
        const int w = r >> 18;
        li = r & (W4 - 1);
        switch (w) {
            case 0: src = Wq; dst = reinterpret_cast<uint2*>(g_wq); break;
            case 1: src = Wk; dst = reinterpret_cast<uint2*>(g_wk); break;
            case 2: src = Wv; dst = reinterpret_cast<uint2*>(g_wv); break;
            default: src = Wo; dst = reinterpret_cast<uint2*>(g_wo); break;
        }
    }
    float4 v = reinterpret_cast<const float4*>(src)[li];
    dst[li] = make_uint2(h2bits(v.x, v.y), h2bits(v.z, v.w));
}

// ---------------------------------------------------------------------------
// FP16 mma.sync GEMM with per-stage mbarrier producer/consumer pipeline
// (no __syncthreads in main loop — warps decouple by up to one chunk).
// CTA 128x64, 128 threads = 4 warps (2m x 2n), warp 64x32, 2 stages,
// fragments via ldmatrix.x4 with cross-k-step double buffering.
// MODE 1 (QKV fused, N=3072); MODE 0 (Wo).
// ---------------------------------------------------------------------------
#define GSTR 36
#define GASTG (128 * GSTR)                   // A u32 per stage
#define GBSTG (64 * GSTR)                    // B u32 per stage
#define GMB   (2 * (GASTG + GBSTG))          // u32 offset of mbarriers
#define GSMEM_BYTES (GMB * 4 + 32)           // stages + 4 mbarriers = 55328 B
#define GNCHUNK 16
#define VT_STR 132                           // halves stride for V transpose

template <int MODE>
__global__ __launch_bounds__(128, 4) void gemm_mma(const uint32_t* __restrict__ A,
                                                   const uint32_t* __restrict__ B0,
                                                   const uint32_t* __restrict__ B1,
                                                   const uint32_t* __restrict__ B2,
                                                   float* __restrict__ Cf,
                                                   uint32_t* __restrict__ Cq,
                                                   uint32_t* __restrict__ Ck,
                                                   uint16_t* __restrict__ Cvt) {
    extern __shared__ uint32_t sm32[];
    const uint32_t as_a = smem_u32(sm32);
    const uint32_t bs_a = as_a + 2 * GASTG * 4;
    const uint32_t mb = as_a + GMB * 4;      // full0, full1, empty0, empty1 (8B each)

    const int tid = threadIdx.x;
    const int bm = blockIdx.y * 128;
    const int bnab = blockIdx.x * 64;

    const uint32_t* B = B0;
    int bn = bnab;
    if (MODE == 1) {
        if (bnab >= 2048)      B = B2;
        else if (bnab >= 1024) B = B1;
        bn = bnab & 1023;
    }

    const int wid = tid >> 5;
    const int lane = tid & 31;
    const int wm = (wid >> 1) * 64;      // 2 m-warps
    const int wn = (wid & 1) * 32;       // 2 n-warps
    const int gid = lane >> 2;
    const int tig = lane & 3;

    // LDSM lane->address mapping (u32 units within a tile row)
    const int a_lrow = (lane & 7) + ((lane >> 3) & 1) * 8;
    const int a_lcol = (lane >> 4) * 4;
    const int b_lrow = (lane & 7) + (lane >> 4) * 8;
    const int b_lcol = ((lane >> 3) & 1) * 4;

    if (tid == 0) {
        MBAR_INIT(mb + 0, 128);   // full0
        MBAR_INIT(mb + 8, 128);   // full1
        MBAR_INIT(mb + 16, 128);  // empty0
        MBAR_INIT(mb + 24, 128);  // empty1
    }
    __syncthreads();

    auto issue_chunk = [&](int c, int buf) {
        const uint32_t ab = as_a + (uint32_t)buf * GASTG * 4;
        const uint32_t bb = bs_a + (uint32_t)buf * GBSTG * 4;
        const int k0 = c * 32;
#pragma unroll
        for (int u = 0; u < 8; u++) {
            const int idx = u * 128 + tid;
            const int r = idx >> 3;
            const int ch = idx & 7;
            cp16(ab + (uint32_t)(r * GSTR + ch * 4) * 4,
                 A + (size_t)(bm + r) * DW32 + k0 + ch * 4);
        }
#pragma unroll
        for (int u = 0; u < 4; u++) {
            const int idx = u * 128 + tid;
            const int r = idx >> 3;
            const int ch = idx & 7;
            cp16(bb + (uint32_t)(r * GSTR + ch * 4) * 4,
                 B + (size_t)(bn + r) * DW32 + k0 + ch * 4);
        }
    };

    float acc[4][4][4];
#pragma unroll
    for (int i = 0; i < 4; i++)
#pragma unroll
        for (int j = 0; j < 4; j++)
#pragma unroll
            for (int r = 0; r < 4; r++) acc[i][j][r] = 0.0f;

    // prologue: fill both stages; full[s] completes when data lands
    issue_chunk(0, 0);
    CP_ARRIVE_NOINC(mb + 0);
    issue_chunk(1, 1);
    CP_ARRIVE_NOINC(mb + 8);

    for (int c = 0; c < GNCHUNK; c++) {
        const int s = c & 1;
        const uint32_t par = (uint32_t)((c >> 1) & 1);
        const uint32_t fullb = mb + (uint32_t)(s * 8);
        const uint32_t emptyb = mb + 16 + (uint32_t)(s * 8);

        mbar_wait_parity(fullb, par);

        const uint32_t aaddr = as_a + (uint32_t)s * GASTG * 4 +
                               (uint32_t)(((wm + a_lrow) * GSTR) + a_lcol) * 4;
        const uint32_t baddr = bs_a + (uint32_t)s * GBSTG * 4 +
                               (uint32_t)(((wn + b_lrow) * GSTR) + b_lcol) * 4;

        uint32_t af[2][4][4], bf[2][4][2];

        auto load_frags = [&](int kk, int d) {
#pragma unroll
            for (int mt = 0; mt < 4; mt++)
                ldsm4(af[d][mt][0], af[d][mt][1], af[d][mt][2], af[d][mt][3],
                      aaddr + (uint32_t)(mt * 16 * GSTR + kk) * 4);
#pragma unroll
            for (int u = 0; u < 2; u++)
                ldsm4(bf[d][2 * u][0], bf[d][2 * u][1],
                      bf[d][2 * u + 1][0], bf[d][2 * u + 1][1],
                      baddr + (uint32_t)(u * 16 * GSTR + kk) * 4);
        };

        load_frags(0, 0);
#pragma unroll
        for (int ks = 0; ks < 4; ks++) {
            const int cur = ks & 1;
            if (ks < 3) load_frags((ks + 1) * 8, cur ^ 1);
            if (ks == 2) MBAR_ARRIVE(emptyb);   // this thread's last LDSM of the chunk done
#pragma unroll
            for (int mt = 0; mt < 4; mt++)
#pragma unroll
                for (int nt = 0; nt < 4; nt++)
                    mma_f16(acc[mt][nt], af[cur][mt], bf[cur][nt]);
        }

        if (c + 2 < GNCHUNK) {
            // wait only for peers' LOADS of this stage (not their compute)
            mbar_wait_parity(emptyb, par);
            issue_chunk(c + 2, s);
            CP_ARRIVE_NOINC(fullb);
        }
    }

    const bool is_q = (MODE == 1) && (bnab < 1024);
    const bool is_v = (MODE == 1) && (bnab >= 2048);

    if (is_v) {
        // ---- V epilogue: transpose via smem, coalesced u32 stores along l ----
        __syncthreads();
        uint16_t* svh = reinterpret_cast<uint16_t*>(sm32);
#pragma unroll
        for (int mt = 0; mt < 4; mt++) {
#pragma unroll
            for (int nt = 0; nt < 4; nt++) {
                const int col = wn + nt * 8 + 2 * tig;
#pragma unroll
                for (int half = 0; half < 2; half++) {
                    const int row = wm + mt * 16 + gid + 8 * half;
                    svh[(col)     * VT_STR + row] = hbits(acc[mt][nt][2 * half]);
                    svh[(col + 1) * VT_STR + row] = hbits(acc[mt][nt][2 * half + 1]);
                }
            }
        }
        __syncthreads();
        const int b = bm >> 11;
        const int bl = bm & (SEQ - 1);
        const int h = bn >> 6;
        const int bh = b * NHEAD + h;
        uint32_t* Cvt32 = reinterpret_cast<uint32_t*>(Cvt);
#pragma unroll
        for (int u = 0; u < 32; u++) {
            const int idx = u * 128 + tid;
            const int dd = idx >> 6;
            const int lc = idx & 63;
            const uint32_t val =
                *reinterpret_cast<const uint32_t*>(&svh[dd * VT_STR + 2 * lc]);
            Cvt32[(((size_t)bh * HDIM + dd) * SEQ + bl + 2 * lc) >> 1] = val;
        }
        return;
    }

#pragma unroll
    for (int mt = 0; mt < 4; mt++) {
        const int row0 = bm + wm + mt * 16 + gid;
#pragma unroll
        for (int nt = 0; nt < 4; nt++) {
            const int gcol = bn + wn + nt * 8 + 2 * tig;
#pragma unroll
            for (int half = 0; half < 2; half++) {
                const int row = row0 + 8 * half;
                float v0 = acc[mt][nt][2 * half];
                float v1 = acc[mt][nt][2 * half + 1];
                if (MODE == 0) {
                    *reinterpret_cast<float2*>(Cf + (size_t)row * DMODEL + gcol) =
                        make_float2(v0, v1);
                } else {
                    const int b = row >> 11;
                    const int l = row & (SEQ - 1);
                    const int h = gcol >> 6;
                    const int dd = gcol & (HDIM - 1);
                    const int bh = b * NHEAD + h;
                    if (is_q) { v0 *= CEXPF; v1 *= CEXPF; }
                    uint32_t* dst = (is_q ? Cq : Ck);
                    dst[((size_t)bh * SEQ + l) * 32 + (dd >> 1)] = h2bits(v0, v1);
                }
            }
        }
    }
}

// ---------------------------------------------------------------------------
// Flash attention, fp16 mma.sync m16n8k16, causal.  (unchanged from R13)
// ---------------------------------------------------------------------------
#define FA_BK 64
#define FA_STR 36
#define FA_ST (64 * FA_STR)
#define FA_SMEM_BYTES (6 * FA_ST * 4)   // 55296 B

__device__ __forceinline__ void fa_load_kv(uint32_t ks_a, uint32_t vs_a,
                                           const uint32_t* Kg, const uint16_t* Vtg,
                                           int k0, int stage, int tid) {
    const uint32_t ko = ks_a + (uint32_t)stage * (FA_ST * 4);
    const uint32_t vo = vs_a + (uint32_t)stage * (FA_ST * 4);
#pragma unroll
    for (int u = 0; u < 2; u++) {
        const int idx = u * 256 + tid;
        const int r = idx >> 3;
        const int ch = idx & 7;
        cp16(ko + (uint32_t)(r * FA_STR + ch * 4) * 4,
             Kg + (size_t)(k0 + r) * 32 + ch * 4);
        cp16(vo + (uint32_t)(r * FA_STR + ch * 4) * 4,
             Vtg + (size_t)r * SEQ + k0 + ch * 8);
    }
}

__global__ __launch_bounds__(256, 2) void flash_mma(const uint32_t* __restrict__ Q,
                                                    const uint32_t* __restrict__ K,
                                                    const uint16_t* __restrict__ Vt,
                                                    uint32_t* __restrict__ ctx) {
    extern __shared__ uint32_t fs32[];
    uint32_t* Ks = fs32;
    uint32_t* Vs = fs32 + 3 * FA_ST;

    const int tid = threadIdx.x;
    const int w = tid >> 5;
    const int lane = tid & 31;
    const int gid = lane >> 2;
    const int tig = lane & 3;
    const int bh = blockIdx.y;
    const int qb = (int)gridDim.x - 1 - (int)blockIdx.x;
    const int q0 = qb * 128;

    const int b_lrow = (lane & 7) + (lane >> 4) * 8;
    const int b_lcol = ((lane >> 3) & 1) * 4;

    const uint32_t* Qg = Q + ((size_t)bh * SEQ + q0) * 32;
    const uint32_t* Kg = K + (size_t)bh * SEQ * 32;
    const uint16_t* Vtg = Vt + (size_t)bh * HDIM * SEQ;

    const uint32_t ks_a = smem_u32(Ks);
    const uint32_t vs_a = smem_u32(Vs);

    const int nkb = 2 * qb + 2;
    const int rq = 16 * w + gid;

    fa_load_kv(ks_a, vs_a, Kg, Vtg, 0, 0, tid);
    asm volatile("cp.async.commit_group;");
    if (nkb > 1) fa_load_kv(ks_a, vs_a, Kg, Vtg, FA_BK, 1, tid);
    asm volatile("cp.async.commit_group;");

    uint32_t qa_all[4][4];
#pragma unroll
    for (int g = 0; g < 4; g++) {
        qa_all[g][0] = Qg[(size_t)rq * 32 + 8 * g + tig];
        qa_all[g][1] = Qg[(size_t)(rq + 8) * 32 + 8 * g + tig];
        qa_all[g][2] = Qg[(size_t)rq * 32 + 8 * g + tig + 4];
        qa_all[g][3] = Qg[(size_t)(rq + 8) * 32 + 8 * g + tig + 4];
    }

    float o[8][4];
#pragma unroll
    for (int nt = 0; nt < 8; nt++)
#pragma unroll
        for (int e = 0; e < 4; e++) o[nt][e] = 0.0f;
    float m0 = -1e30f, m1 = -1e30f, l0 = 0.0f, l1 = 0.0f;

    for (int kb = 0; kb < nkb; kb++) {
        asm volatile("cp.async.wait_group 1;");
        __syncthreads();
        if (kb + 2 < nkb) fa_load_kv(ks_a, vs_a, Kg, Vtg, (kb + 2) * FA_BK, (kb + 2) % 3, tid);
        asm volatile("cp.async.commit_group;");

        const int k0 = kb * FA_BK;
        if (k0 > q0 + 16 * w + 15) continue;   // fully-masked warp-block

        const int buf = kb % 3;
        const uint32_t kaddr = ks_a + (uint32_t)buf * FA_ST * 4 +
                               (uint32_t)(b_lrow * FA_STR + b_lcol) * 4;
        const uint32_t vaddr = vs_a + (uint32_t)buf * FA_ST * 4 +
                               (uint32_t)(b_lrow * FA_STR + b_lcol) * 4;

        float c[8][4];
#pragma unroll
        for (int nt = 0; nt < 8; nt++)
#pragma unroll
            for (int e = 0; e < 4; e++) c[nt][e] = 0.0f;

#pragma unroll
        for (int g = 0; g < 4; g++) {
            uint32_t kf[8][2];
#pragma unroll
            for (int u = 0; u < 4; u++)
                ldsm4(kf[2 * u][0], kf[2 * u][1], kf[2 * u + 1][0], kf[2 * u + 1][1],
                      kaddr + (uint32_t)(u * 16 * FA_STR + 8 * g) * 4);
#pragma unroll
            for (int nt = 0; nt < 8; nt++) mma_f16(c[nt], qa_all[g], kf[nt]);
        }

        if (k0 + 63 > q0 + 16 * w) {
            const int r0g = q0 + rq;
#pragma unroll
            for (int nt = 0; nt < 8; nt++) {
                const int cb = k0 + 8 * nt + 2 * tig;
                if (cb > r0g) c[nt][0] = -1e30f;
                if (cb + 1 > r0g) c[nt][1] = -1e30f;
                if (cb > r0g + 8) c[nt][2] = -1e30f;
                if (cb + 1 > r0g + 8) c[nt][3] = -1e30f;
            }
        }

        float mx0 = -1e30f, mx1 = -1e30f;
#pragma unroll
        for (int nt = 0; nt < 8; nt++) {
            mx0 = fmaxf(mx0, fmaxf(c[nt][0], c[nt][1]));
            mx1 = fmaxf(mx1, fmaxf(c[nt][2], c[nt][3]));
        }
        mx0 = fmaxf(mx0, __shfl_xor_sync(0xffffffffu, mx0, 1));
        mx0 = fmaxf(mx0, __shfl_xor_sync(0xffffffffu, mx0, 2));
        mx1 = fmaxf(mx1, __shfl_xor_sync(0xffffffffu, mx1, 1));
        mx1 = fmaxf(mx1, __shfl_xor_sync(0xffffffffu, mx1, 2));

        const float mn0 = fmaxf(fmaxf(m0, mx0), -1000.0f);
        const float mn1 = fmaxf(fmaxf(m1, mx1), -1000.0f);
        const float corr0 = ex2(m0 - mn0);
        const float corr1 = ex2(m1 - mn1);

        float rs0 = 0.0f, rs1 = 0.0f;
        uint32_t pw[8][2];
#pragma unroll
        for (int nt = 0; nt < 8; nt++) {
            const float p0 = ex2(c[nt][0] - mn0);
            const float p1 = ex2(c[nt][1] - mn0);
            const float p2 = ex2(c[nt][2] - mn1);
            const float p3 = ex2(c[nt][3] - mn1);
            rs0 += p0 + p1;
            rs1 += p2 + p3;
            pw[nt][0] = h2bits(p0, p1);
            pw[nt][1] = h2bits(p2, p3);
        }

#pragma unroll
        for (int nt = 0; nt < 8; nt++) {
            o[nt][0] *= corr0;
            o[nt][1] *= corr0;
            o[nt][2] *= corr1;
            o[nt][3] *= corr1;
        }

#pragma unroll
        for (int j = 0; j < 4; j++) {
            uint32_t pa[4] = {pw[2 * j][0], pw[2 * j][1],
                              pw[2 * j + 1][0], pw[2 * j + 1][1]};
            uint32_t vf[8][2];
#pragma unroll
            for (int u = 0; u < 4; u++)
                ldsm4(vf[2 * u][0], vf[2 * u][1], vf[2 * u + 1][0], vf[2 * u + 1][1],
                      vaddr + (uint32_t)(u * 16 * FA_STR + 8 * j) * 4);
#pragma unroll
            for (int nt = 0; nt < 8; nt++) mma_f16(o[nt], pa, vf[nt]);
        }

        rs0 += __shfl_xor_sync(0xffffffffu, rs0, 1);
        rs0 += __shfl_xor_sync(0xffffffffu, rs0, 2);
        rs1 += __shfl_xor_sync(0xffffffffu, rs1, 1);
        rs1 += __shfl_xor_sync(0xffffffffu, rs1, 2);
        l0 = l0 * corr0 + rs0;
        l1 = l1 * corr1 + rs1;
        m0 = mn0;
        m1 = mn1;
    }

    const float inv0 = 1.0f / l0;
    const float inv1 = 1.0f / l1;
    const int b = bh >> 4;
    const int h = bh & 15;
    const int r0 = q0 + rq;
#pragma unroll
    for (int nt = 0; nt < 8; nt++) {
        const int ci = h * 32 + 4 * nt + tig;
        ctx[((size_t)(b * SEQ + r0)) * DW32 + ci] = h2bits(o[nt][0] * inv0, o[nt][1] * inv0);
        ctx[((size_t)(b * SEQ + r0 + 8)) * DW32 + ci] = h2bits(o[nt][2] * inv1, o[nt][3] * inv1);
    }
}

// ---------------------------------------------------------------------------
// Launch
// ---------------------------------------------------------------------------
template <typename T>
static T* sym_addr(const void* symbol) {
    void* p = nullptr;
    cudaGetSymbolAddress(&p, symbol);
    return reinterpret_cast<T*>(p);
}

extern "C" void kernel_launch(void* const* d_in, const int* in_sizes, int n_in,
                              void* d_out, int out_size) {
    const float* x  = (const float*)d_in[0];
    const float* Wq = (const float*)d_in[1];
    const float* Wk = (const float*)d_in[2];
    const float* Wv = (const float*)d_in[3];
    const float* Wo = (const float*)d_in[4];
    float* out = (float*)d_out;

    uint32_t* xr = sym_addr<uint32_t>(g_xr);
    uint32_t* wq = sym_addr<uint32_t>(g_wq);
    uint32_t* wk = sym_addr<uint32_t>(g_wk);
    uint32_t* wv = sym_addr<uint32_t>(g_wv);
    uint32_t* wo = sym_addr<uint32_t>(g_wo);
    uint32_t* q  = sym_addr<uint32_t>(g_q);
    uint32_t* k  = sym_addr<uint32_t>(g_k);
    uint16_t* vt = sym_addr<uint16_t>(g_vt);
    uint32_t* ctx = sym_addr<uint32_t>(g_ctx);

    cudaFuncSetAttribute(gemm_mma<1>, cudaFuncAttributeMaxDynamicSharedMemorySize, GSMEM_BYTES);
    cudaFuncSetAttribute(gemm_mma<0>, cudaFuncAttributeMaxDynamicSharedMemorySize, GSMEM_BYTES);
    cudaFuncSetAttribute(flash_mma, cudaFuncAttributeMaxDynamicSharedMemorySize, FA_SMEM_BYTES);

    round_pack<<<(TOTAL4 + 255) / 256, 256>>>(x, Wq, Wk, Wv, Wo);

    dim3 gqkv(3 * DMODEL / 64, MTOT / 128);    // (48, 32) = 1536 CTAs
    gemm_mma<1><<<gqkv, 128, GSMEM_BYTES>>>(xr, wq, wk, wv, nullptr, q, k, vt);

    dim3 ga(SEQ / 128, BATCH * NHEAD);         // (16, 32)
    flash_mma<<<ga, 256, FA_SMEM_BYTES>>>(q, k, vt, ctx);

    dim3 go(DMODEL / 64, MTOT / 128);          // (16, 32) = 512 CTAs
    gemm_mma<0><<<go, 128, GSMEM_BYTES>>>(ctx, wo, nullptr, nullptr, out, nullptr, nullptr, nullptr);
}

// round 15
// speedup vs baseline: 1.0341x; 1.0004x over previous
#include <cuda_runtime.h>
#include <cuda_fp16.h>
#include <cstdint>

// ---------------------------------------------------------------------------
// Problem constants: B=2, L=2048, D=1024, H=16, hd=64
// ---------------------------------------------------------------------------
#define BATCH 2
#define SEQ   2048
#define DMODEL 1024
#define NHEAD 16
#define HDIM  64
#define MTOT  (BATCH * SEQ)          // 4096
#define CEXPF 0.1803368801111f       // 0.125 * log2(e), folded into q
#define DW32  (DMODEL / 2)           // 512 uint32 (half2) per row

// Scratch (device globals). All fp16 operands stored half2-packed as uint32.
__device__ uint32_t g_xr[MTOT * DW32];
__device__ uint32_t g_wq[DMODEL * DW32];
__device__ uint32_t g_wk[DMODEL * DW32];
__device__ uint32_t g_wv[DMODEL * DW32];
__device__ uint32_t g_wo[DMODEL * DW32];
__device__ uint32_t g_q[MTOT * DMODEL / 2];    // [b*16+h][l][32 u32]
__device__ uint32_t g_k[MTOT * DMODEL / 2];
__device__ uint16_t g_vt[MTOT * DMODEL];       // [b*16+h][hd][l] halves
__device__ uint32_t g_ctx[MTOT * DW32];        // [b*SEQ+l][512 u32]

__device__ __forceinline__ float ex2(float x) {
    float r;
    asm("ex2.approx.f32 %0, %1;" : "=f"(r) : "f"(x));
    return r;
}
__device__ __forceinline__ uint32_t smem_u32(const void* p) {
    uint32_t a;
    asm("{ .reg .u64 t; cvta.to.shared.u64 t, %1; cvt.u32.u64 %0, t; }" : "=r"(a) : "l"(p));
    return a;
}
__device__ __forceinline__ void cp16(uint32_t smem, const void* g) {
    asm volatile("cp.async.cg.shared.global [%0], [%1], 16;"
                 :: "r"(smem), "l"(__cvta_generic_to_global(g)));
}
__device__ __forceinline__ void mma_f16(float* d, const uint32_t* a, const uint32_t* b) {
    asm volatile(
        "mma.sync.aligned.m16n8k16.row.col.f32.f16.f16.f32 "
        "{%0,%1,%2,%3}, {%4,%5,%6,%7}, {%8,%9}, {%0,%1,%2,%3};\n"
        : "+f"(d[0]), "+f"(d[1]), "+f"(d[2]), "+f"(d[3])
        : "r"(a[0]), "r"(a[1]), "r"(a[2]), "r"(a[3]), "r"(b[0]), "r"(b[1]));
}
__device__ __forceinline__ void ldsm4(uint32_t& r0, uint32_t& r1, uint32_t& r2,
                                      uint32_t& r3, uint32_t a) {
    asm volatile("ldmatrix.sync.aligned.m8n8.x4.shared.b16 {%0,%1,%2,%3}, [%4];"
                 : "=r"(r0), "=r"(r1), "=r"(r2), "=r"(r3) : "r"(a));
}
__device__ __forceinline__ uint32_t h2bits(float a, float b) {
    __half2 h = __floats2half2_rn(a, b);
    return *reinterpret_cast<uint32_t*>(&h);
}
__device__ __forceinline__ uint16_t hbits(float a) {
    __half h = __float2half_rn(a);
    return *reinterpret_cast<uint16_t*>(&h);
}

// ---- mbarrier helpers (plain sm_100 PTX, no 'a' features) ----
#define MBAR_INIT(addr, cnt) \
    asm volatile("mbarrier.init.shared.b64 [%0], %1;" :: "r"(addr), "r"((uint32_t)(cnt)) : "memory")
#define MBAR_ARRIVE(addr) \
    asm volatile("mbarrier.arrive.shared.b64 _, [%0];" :: "r"(addr) : "memory")
#define CP_ARRIVE_NOINC(addr) \
    asm volatile("cp.async.mbarrier.arrive.noinc.shared::cta.b64 [%0];" :: "r"(addr) : "memory")

__device__ __forceinline__ void mbar_wait_parity(uint32_t mbar, uint32_t parity) {
    uint32_t done;
    asm volatile(
        "{\n\t.reg .pred p;\n\t"
        "mbarrier.try_wait.parity.shared.b64 p, [%1], %2;\n\t"
        "selp.b32 %0, 1, 0, p;\n\t}"
        : "=r"(done) : "r"(mbar), "r"(parity) : "memory");
    if (!done) {
        asm volatile(
            "{\n\t.reg .pred P1;\n\t"
            "W_%=:\n\t"
            "mbarrier.try_wait.parity.shared.b64 P1, [%0], %1;\n\t"
            "@P1 bra.uni D_%=;\n\t"
            "bra.uni W_%=;\n\t"
            "D_%=:\n\t}"
            :: "r"(mbar), "r"(parity) : "memory");
    }
}

// ---------------------------------------------------------------------------
// Fused fp16 round+pack of x and all 4 weights, 4-way MLP per thread.
// (R6 profile showed the 1-load/thread version latency-bound at 1.5 TB/s.)
// ---------------------------------------------------------------------------
#define X4 (MTOT * DMODEL / 4)
#define W4 (DMODEL * DMODEL / 4)
#define TOTAL4 (X4 + 4 * W4)          // 2097152 float4 elements
#define RP_CTAS 2048                  // 2048*256*4 = TOTAL4 exactly

__global__ __launch_bounds__(256) void round_pack(
    const float* __restrict__ x, const float* __restrict__ Wq,
    const float* __restrict__ Wk, const float* __restrict__ Wv,
    const float* __restrict__ Wo) {
    const int base = blockIdx.x * 1024 + threadIdx.x;   // 4 slots, stride 256

    const float* srcs[4];
    uint2* dsts[4];
    int lis[4];
#pragma unroll
    for (int u = 0; u < 4; u++) {
        const int idx = base + u * 256;
        if (idx < X4) {
            srcs[u] = x; dsts[u] = reinterpret_cast<uint2*>(g_xr); lis[u] = idx;
        } else {
            const int r = idx - X4;
            const int w = r >> 18;
            lis[u] = r & (W4 - 1);
            switch (w) {
                case 0: srcs[u] = Wq; dsts[u] = reinterpret_cast<uint2*>(g_wq); break;
                case 1: srcs[u] = Wk; dsts[u] = reinterpret_cast<uint2*>(g_wk); break;
                case 2: srcs[u] = Wv; dsts[u] = reinterpret_cast<uint2*>(g_wv); break;
                default: srcs[u] = Wo; dsts[u] = reinterpret_cast<uint2*>(g_wo); break;
            }
        }
    }

    // front-batched independent loads (MLP = 4)
    float4 v[4];
#pragma unroll
    for (int u = 0; u < 4; u++)
        v[u] = reinterpret_cast<const float4*>(srcs[u])[lis[u]];

#pragma unroll
    for (int u = 0; u < 4; u++)
        dsts[u][lis[u]] = make_uint2(h2bits(v[u].x, v[u].y), h2bits(v[u].z, v[u].w));
}

// ---------------------------------------------------------------------------
// FP16 mma.sync GEMM with per-stage mbarrier producer/consumer pipeline
// (no __syncthreads in main loop — warps decouple by up to one chunk).
// CTA 128x64, 128 threads = 4 warps (2m x 2n), warp 64x32, 2 stages,
// fragments via ldmatrix.x4 with cross-k-step double buffering.
// MODE 1 (QKV fused, N=3072); MODE 0 (Wo).
// ---------------------------------------------------------------------------
#define GSTR 36
#define GASTG (128 * GSTR)                   // A u32 per stage
#define GBSTG (64 * GSTR)                    // B u32 per stage
#define GMB   (2 * (GASTG + GBSTG))          // u32 offset of mbarriers
#define GSMEM_BYTES (GMB * 4 + 32)           // stages + 4 mbarriers = 55328 B
#define GNCHUNK 16
#define VT_STR 132                           // halves stride for V transpose

template <int MODE>
__global__ __launch_bounds__(128, 4) void gemm_mma(const uint32_t* __restrict__ A,
                                                   const uint32_t* __restrict__ B0,
                                                   const uint32_t* __restrict__ B1,
                                                   const uint32_t* __restrict__ B2,
                                                   float* __restrict__ Cf,
                                                   uint32_t* __restrict__ Cq,
                                                   uint32_t* __restrict__ Ck,
                                                   uint16_t* __restrict__ Cvt) {
    extern __shared__ uint32_t sm32[];
    const uint32_t as_a = smem_u32(sm32);
    const uint32_t bs_a = as_a + 2 * GASTG * 4;
    const uint32_t mb = as_a + GMB * 4;      // full0, full1, empty0, empty1 (8B each)

    const int tid = threadIdx.x;
    const int bm = blockIdx.y * 128;
    const int bnab = blockIdx.x * 64;

    const uint32_t* B = B0;
    int bn = bnab;
    if (MODE == 1) {
        if (bnab >= 2048)      B = B2;
        else if (bnab >= 1024) B = B1;
        bn = bnab & 1023;
    }

    const int wid = tid >> 5;
    const int lane = tid & 31;
    const int wm = (wid >> 1) * 64;      // 2 m-warps
    const int wn = (wid & 1) * 32;       // 2 n-warps
    const int gid = lane >> 2;
    const int tig = lane & 3;

    // LDSM lane->address mapping (u32 units within a tile row)
    const int a_lrow = (lane & 7) + ((lane >> 3) & 1) * 8;
    const int a_lcol = (lane >> 4) * 4;
    const int b_lrow = (lane & 7) + (lane >> 4) * 8;
    const int b_lcol = ((lane >> 3) & 1) * 4;

    if (tid == 0) {
        MBAR_INIT(mb + 0, 128);   // full0
        MBAR_INIT(mb + 8, 128);   // full1
        MBAR_INIT(mb + 16, 128);  // empty0
        MBAR_INIT(mb + 24, 128);  // empty1
    }
    __syncthreads();

    auto issue_chunk = [&](int c, int buf) {
        const uint32_t ab = as_a + (uint32_t)buf * GASTG * 4;
        const uint32_t bb = bs_a + (uint32_t)buf * GBSTG * 4;
        const int k0 = c * 32;
#pragma unroll
        for (int u = 0; u < 8; u++) {
            const int idx = u * 128 + tid;
            const int r = idx >> 3;
            const int ch = idx & 7;
            cp16(ab + (uint32_t)(r * GSTR + ch * 4) * 4,
                 A + (size_t)(bm + r) * DW32 + k0 + ch * 4);
        }
#pragma unroll
        for (int u = 0; u < 4; u++) {
            const int idx = u * 128 + tid;
            const int r = idx >> 3;
            const int ch = idx & 7;
            cp16(bb + (uint32_t)(r * GSTR + ch * 4) * 4,
                 B + (size_t)(bn + r) * DW32 + k0 + ch * 4);
        }
    };

    float acc[4][4][4];
#pragma unroll
    for (int i = 0; i < 4; i++)
#pragma unroll
        for (int j = 0; j < 4; j++)
#pragma unroll
            for (int r = 0; r < 4; r++) acc[i][j][r] = 0.0f;

    // prologue: fill both stages; full[s] completes when data lands
    issue_chunk(0, 0);
    CP_ARRIVE_NOINC(mb + 0);
    issue_chunk(1, 1);
    CP_ARRIVE_NOINC(mb + 8);

    for (int c = 0; c < GNCHUNK; c++) {
        const int s = c & 1;
        const uint32_t par = (uint32_t)((c >> 1) & 1);
        const uint32_t fullb = mb + (uint32_t)(s * 8);
        const uint32_t emptyb = mb + 16 + (uint32_t)(s * 8);

        mbar_wait_parity(fullb, par);

        const uint32_t aaddr = as_a + (uint32_t)s * GASTG * 4 +
                               (uint32_t)(((wm + a_lrow) * GSTR) + a_lcol) * 4;
        const uint32_t baddr = bs_a + (uint32_t)s * GBSTG * 4 +
                               (uint32_t)(((wn + b_lrow) * GSTR) + b_lcol) * 4;

        uint32_t af[2][4][4], bf[2][4][2];

        auto load_frags = [&](int kk, int d) {
#pragma unroll
            for (int mt = 0; mt < 4; mt++)
                ldsm4(af[d][mt][0], af[d][mt][1], af[d][mt][2], af[d][mt][3],
                      aaddr + (uint32_t)(mt * 16 * GSTR + kk) * 4);
#pragma unroll
            for (int u = 0; u < 2; u++)
                ldsm4(bf[d][2 * u][0], bf[d][2 * u][1],
                      bf[d][2 * u + 1][0], bf[d][2 * u + 1][1],
                      baddr + (uint32_t)(u * 16 * GSTR + kk) * 4);
        };

        load_frags(0, 0);
#pragma unroll
        for (int ks = 0; ks < 4; ks++) {
            const int cur = ks & 1;
            if (ks < 3) load_frags((ks + 1) * 8, cur ^ 1);
            if (ks == 2) MBAR_ARRIVE(emptyb);   // this thread's last LDSM of the chunk done
#pragma unroll
            for (int mt = 0; mt < 4; mt++)
#pragma unroll
                for (int nt = 0; nt < 4; nt++)
                    mma_f16(acc[mt][nt], af[cur][mt], bf[cur][nt]);
        }

        if (c + 2 < GNCHUNK) {
            // wait only for peers' LOADS of this stage (not their compute)
            mbar_wait_parity(emptyb, par);
            issue_chunk(c + 2, s);
            CP_ARRIVE_NOINC(fullb);
        }
    }

    const bool is_q = (MODE == 1) && (bnab < 1024);
    const bool is_v = (MODE == 1) && (bnab >= 2048);

    if (is_v) {
        // ---- V epilogue: transpose via smem, coalesced u32 stores along l ----
        __syncthreads();
        uint16_t* svh = reinterpret_cast<uint16_t*>(sm32);
#pragma unroll
        for (int mt = 0; mt < 4; mt++) {
#pragma unroll
            for (int nt = 0; nt < 4; nt++) {
                const int col = wn + nt * 8 + 2 * tig;
#pragma unroll
                for (int half = 0; half < 2; half++) {
                    const int row = wm + mt * 16 + gid + 8 * half;
                    svh[(col)     * VT_STR + row] = hbits(acc[mt][nt][2 * half]);
                    svh[(col + 1) * VT_STR + row] = hbits(acc[mt][nt][2 * half + 1]);
                }
            }
        }
        __syncthreads();
        const int b = bm >> 11;
        const int bl = bm & (SEQ - 1);
        const int h = bn >> 6;
        const int bh = b * NHEAD + h;
        uint32_t* Cvt32 = reinterpret_cast<uint32_t*>(Cvt);
#pragma unroll
        for (int u = 0; u < 32; u++) {
            const int idx = u * 128 + tid;
            const int dd = idx >> 6;
            const int lc = idx & 63;
            const uint32_t val =
                *reinterpret_cast<const uint32_t*>(&svh[dd * VT_STR + 2 * lc]);
            Cvt32[(((size_t)bh * HDIM + dd) * SEQ + bl + 2 * lc) >> 1] = val;
        }
        return;
    }

#pragma unroll
    for (int mt = 0; mt < 4; mt++) {
        const int row0 = bm + wm + mt * 16 + gid;
#pragma unroll
        for (int nt = 0; nt < 4; nt++) {
            const int gcol = bn + wn + nt * 8 + 2 * tig;
#pragma unroll
            for (int half = 0; half < 2; half++) {
                const int row = row0 + 8 * half;
                float v0 = acc[mt][nt][2 * half];
                float v1 = acc[mt][nt][2 * half + 1];
                if (MODE == 0) {
                    *reinterpret_cast<float2*>(Cf + (size_t)row * DMODEL + gcol) =
                        make_float2(v0, v1);
                } else {
                    const int b = row >> 11;
                    const int l = row & (SEQ - 1);
                    const int h = gcol >> 6;
                    const int dd = gcol & (HDIM - 1);
                    const int bh = b * NHEAD + h;
                    if (is_q) { v0 *= CEXPF; v1 *= CEXPF; }
                    uint32_t* dst = (is_q ? Cq : Ck);
                    dst[((size_t)bh * SEQ + l) * 32 + (dd >> 1)] = h2bits(v0, v1);
                }
            }
        }
    }
}

// ---------------------------------------------------------------------------
// Flash attention, fp16 mma.sync m16n8k16, causal.  (unchanged from R14)
// ---------------------------------------------------------------------------
#define FA_BK 64
#define FA_STR 36
#define FA_ST (64 * FA_STR)
#define FA_SMEM_BYTES (6 * FA_ST * 4)   // 55296 B

__device__ __forceinline__ void fa_load_kv(uint32_t ks_a, uint32_t vs_a,
                                           const uint32_t* Kg, const uint16_t* Vtg,
                                           int k0, int stage, int tid) {
    const uint32_t ko = ks_a + (uint32_t)stage * (FA_ST * 4);
    const uint32_t vo = vs_a + (uint32_t)stage * (FA_ST * 4);
#pragma unroll
    for (int u = 0; u < 2; u++) {
        const int idx = u * 256 + tid;
        const int r = idx >> 3;
        const int ch = idx & 7;
        cp16(ko + (uint32_t)(r * FA_STR + ch * 4) * 4,
             Kg + (size_t)(k0 + r) * 32 + ch * 4);
        cp16(vo + (uint32_t)(r * FA_STR + ch * 4) * 4,
             Vtg + (size_t)r * SEQ + k0 + ch * 8);
    }
}

__global__ __launch_bounds__(256, 2) void flash_mma(const uint32_t* __restrict__ Q,
                                                    const uint32_t* __restrict__ K,
                                                    const uint16_t* __restrict__ Vt,
                                                    uint32_t* __restrict__ ctx) {
    extern __shared__ uint32_t fs32[];
    uint32_t* Ks = fs32;
    uint32_t* Vs = fs32 + 3 * FA_ST;

    const int tid = threadIdx.x;
    const int w = tid >> 5;
    const int lane = tid & 31;
    const int gid = lane >> 2;
    const int tig = lane & 3;
    const int bh = blockIdx.y;
    const int qb = (int)gridDim.x - 1 - (int)blockIdx.x;
    const int q0 = qb * 128;

    const int b_lrow = (lane & 7) + (lane >> 4) * 8;
    const int b_lcol = ((lane >> 3) & 1) * 4;

    const uint32_t* Qg = Q + ((size_t)bh * SEQ + q0) * 32;
    const uint32_t* Kg = K + (size_t)bh * SEQ * 32;
    const uint16_t* Vtg = Vt + (size_t)bh * HDIM * SEQ;

    const uint32_t ks_a = smem_u32(Ks);
    const uint32_t vs_a = smem_u32(Vs);

    const int nkb = 2 * qb + 2;
    const int rq = 16 * w + gid;

    fa_load_kv(ks_a, vs_a, Kg, Vtg, 0, 0, tid);
    asm volatile("cp.async.commit_group;");
    if (nkb > 1) fa_load_kv(ks_a, vs_a, Kg, Vtg, FA_BK, 1, tid);
    asm volatile("cp.async.commit_group;");

    uint32_t qa_all[4][4];
#pragma unroll
    for (int g = 0; g < 4; g++) {
        qa_all[g][0] = Qg[(size_t)rq * 32 + 8 * g + tig];
        qa_all[g][1] = Qg[(size_t)(rq + 8) * 32 + 8 * g + tig];
        qa_all[g][2] = Qg[(size_t)rq * 32 + 8 * g + tig + 4];
        qa_all[g][3] = Qg[(size_t)(rq + 8) * 32 + 8 * g + tig + 4];
    }

    float o[8][4];
#pragma unroll
    for (int nt = 0; nt < 8; nt++)
#pragma unroll
        for (int e = 0; e < 4; e++) o[nt][e] = 0.0f;
    float m0 = -1e30f, m1 = -1e30f, l0 = 0.0f, l1 = 0.0f;

    for (int kb = 0; kb < nkb; kb++) {
        asm volatile("cp.async.wait_group 1;");
        __syncthreads();
        if (kb + 2 < nkb) fa_load_kv(ks_a, vs_a, Kg, Vtg, (kb + 2) * FA_BK, (kb + 2) % 3, tid);
        asm volatile("cp.async.commit_group;");

        const int k0 = kb * FA_BK;
        if (k0 > q0 + 16 * w + 15) continue;   // fully-masked warp-block

        const int buf = kb % 3;
        const uint32_t kaddr = ks_a + (uint32_t)buf * FA_ST * 4 +
                               (uint32_t)(b_lrow * FA_STR + b_lcol) * 4;
        const uint32_t vaddr = vs_a + (uint32_t)buf * FA_ST * 4 +
                               (uint32_t)(b_lrow * FA_STR + b_lcol) * 4;

        float c[8][4];
#pragma unroll
        for (int nt = 0; nt < 8; nt++)
#pragma unroll
            for (int e = 0; e < 4; e++) c[nt][e] = 0.0f;

#pragma unroll
        for (int g = 0; g < 4; g++) {
            uint32_t kf[8][2];
#pragma unroll
            for (int u = 0; u < 4; u++)
                ldsm4(kf[2 * u][0], kf[2 * u][1], kf[2 * u + 1][0], kf[2 * u + 1][1],
                      kaddr + (uint32_t)(u * 16 * FA_STR + 8 * g) * 4);
#pragma unroll
            for (int nt = 0; nt < 8; nt++) mma_f16(c[nt], qa_all[g], kf[nt]);
        }

        if (k0 + 63 > q0 + 16 * w) {
            const int r0g = q0 + rq;
#pragma unroll
            for (int nt = 0; nt < 8; nt++) {
                const int cb = k0 + 8 * nt + 2 * tig;
                if (cb > r0g) c[nt][0] = -1e30f;
                if (cb + 1 > r0g) c[nt][1] = -1e30f;
                if (cb > r0g + 8) c[nt][2] = -1e30f;
                if (cb + 1 > r0g + 8) c[nt][3] = -1e30f;
            }
        }

        float mx0 = -1e30f, mx1 = -1e30f;
#pragma unroll
        for (int nt = 0; nt < 8; nt++) {
            mx0 = fmaxf(mx0, fmaxf(c[nt][0], c[nt][1]));
            mx1 = fmaxf(mx1, fmaxf(c[nt][2], c[nt][3]));
        }
        mx0 = fmaxf(mx0, __shfl_xor_sync(0xffffffffu, mx0, 1));
        mx0 = fmaxf(mx0, __shfl_xor_sync(0xffffffffu, mx0, 2));
        mx1 = fmaxf(mx1, __shfl_xor_sync(0xffffffffu, mx1, 1));
        mx1 = fmaxf(mx1, __shfl_xor_sync(0xffffffffu, mx1, 2));

        const float mn0 = fmaxf(fmaxf(m0, mx0), -1000.0f);
        const float mn1 = fmaxf(fmaxf(m1, mx1), -1000.0f);
        const float corr0 = ex2(m0 - mn0);
        const float corr1 = ex2(m1 - mn1);

        float rs0 = 0.0f, rs1 = 0.0f;
        uint32_t pw[8][2];
#pragma unroll
        for (int nt = 0; nt < 8; nt++) {
            const float p0 = ex2(c[nt][0] - mn0);
            const float p1 = ex2(c[nt][1] - mn0);
            const float p2 = ex2(c[nt][2] - mn1);
            const float p3 = ex2(c[nt][3] - mn1);
            rs0 += p0 + p1;
            rs1 += p2 + p3;
            pw[nt][0] = h2bits(p0, p1);
            pw[nt][1] = h2bits(p2, p3);
        }

#pragma unroll
        for (int nt = 0; nt < 8; nt++) {
            o[nt][0] *= corr0;
            o[nt][1] *= corr0;
            o[nt][2] *= corr1;
            o[nt][3] *= corr1;
        }

#pragma unroll
        for (int j = 0; j < 4; j++) {
            uint32_t pa[4] = {pw[2 * j][0], pw[2 * j][1],
                              pw[2 * j + 1][0], pw[2 * j + 1][1]};
            uint32_t vf[8][2];
#pragma unroll
            for (int u = 0; u < 4; u++)
                ldsm4(vf[2 * u][0], vf[2 * u][1], vf[2 * u + 1][0], vf[2 * u + 1][1],
                      vaddr + (uint32_t)(u * 16 * FA_STR + 8 * j) * 4);
#pragma unroll
            for (int nt = 0; nt < 8; nt++) mma_f16(o[nt], pa, vf[nt]);
        }

        rs0 += __shfl_xor_sync(0xffffffffu, rs0, 1);
        rs0 += __shfl_xor_sync(0xffffffffu, rs0, 2);
        rs1 += __shfl_xor_sync(0xffffffffu, rs1, 1);
        rs1 += __shfl_xor_sync(0xffffffffu, rs1, 2);
        l0 = l0 * corr0 + rs0;
        l1 = l1 * corr1 + rs1;
        m0 = mn0;
        m1 = mn1;
    }

    const float inv0 = 1.0f / l0;
    const float inv1 = 1.0f / l1;
    const int b = bh >> 4;
    const int h = bh & 15;
    const int r0 = q0 + rq;
#pragma unroll
    for (int nt = 0; nt < 8; nt++) {
        const int ci = h * 32 + 4 * nt + tig;
        ctx[((size_t)(b * SEQ + r0)) * DW32 + ci] = h2bits(o[nt][0] * inv0, o[nt][1] * inv0);
        ctx[((size_t)(b * SEQ + r0 + 8)) * DW32 + ci] = h2bits(o[nt][2] * inv1, o[nt][3] * inv1);
    }
}

// ---------------------------------------------------------------------------
// Launch
// ---------------------------------------------------------------------------
template <typename T>
static T* sym_addr(const void* symbol) {
    void* p = nullptr;
    cudaGetSymbolAddress(&p, symbol);
    return reinterpret_cast<T*>(p);
}

extern "C" void kernel_launch(void* const* d_in, const int* in_sizes, int n_in,
                              void* d_out, int out_size) {
    const float* x  = (const float*)d_in[0];
    const float* Wq = (const float*)d_in[1];
    const float* Wk = (const float*)d_in[2];
    const float* Wv = (const float*)d_in[3];
    const float* Wo = (const float*)d_in[4];
    float* out = (float*)d_out;

    uint32_t* xr = sym_addr<uint32_t>(g_xr);
    uint32_t* wq = sym_addr<uint32_t>(g_wq);
    uint32_t* wk = sym_addr<uint32_t>(g_wk);
    uint32_t* wv = sym_addr<uint32_t>(g_wv);
    uint32_t* wo = sym_addr<uint32_t>(g_wo);
    uint32_t* q  = sym_addr<uint32_t>(g_q);
    uint32_t* k  = sym_addr<uint32_t>(g_k);
    uint16_t* vt = sym_addr<uint16_t>(g_vt);
    uint32_t* ctx = sym_addr<uint32_t>(g_ctx);

    cudaFuncSetAttribute(gemm_mma<1>, cudaFuncAttributeMaxDynamicSharedMemorySize, GSMEM_BYTES);
    cudaFuncSetAttribute(gemm_mma<0>, cudaFuncAttributeMaxDynamicSharedMemorySize, GSMEM_BYTES);
    cudaFuncSetAttribute(flash_mma, cudaFuncAttributeMaxDynamicSharedMemorySize, FA_SMEM_BYTES);

    round_pack<<<RP_CTAS, 256>>>(x, Wq, Wk, Wv, Wo);

    dim3 gqkv(3 * DMODEL / 64, MTOT / 128);    // (48, 32) = 1536 CTAs
    gemm_mma<1><<<gqkv, 128, GSMEM_BYTES>>>(xr, wq, wk, wv, nullptr, q, k, vt);

    dim3 ga(SEQ / 128, BATCH * NHEAD);         // (16, 32)
    flash_mma<<<ga, 256, FA_SMEM_BYTES>>>(q, k, vt, ctx);

    dim3 go(DMODEL / 64, MTOT / 128);          // (16, 32) = 512 CTAs
    gemm_mma<0><<<go, 128, GSMEM_BYTES>>>(ctx, wo, nullptr, nullptr, out, nullptr, nullptr, nullptr);
}

// round 16
// speedup vs baseline: 1.0615x; 1.0265x over previous
#include <cuda_runtime.h>
#include <cuda_fp16.h>
#include <cstdint>

// ---------------------------------------------------------------------------
// Problem constants: B=2, L=2048, D=1024, H=16, hd=64
// ---------------------------------------------------------------------------
#define BATCH 2
#define SEQ   2048
#define DMODEL 1024
#define NHEAD 16
#define HDIM  64
#define MTOT  (BATCH * SEQ)          // 4096
#define CEXPF 0.1803368801111f       // 0.125 * log2(e), folded into q
#define DW32  (DMODEL / 2)           // 512 uint32 (half2) per row

// Scratch (device globals). All fp16 operands stored half2-packed as uint32.
__device__ uint32_t g_xr[MTOT * DW32];
__device__ uint32_t g_wq[DMODEL * DW32];
__device__ uint32_t g_wk[DMODEL * DW32];
__device__ uint32_t g_wv[DMODEL * DW32];
__device__ uint32_t g_wo[DMODEL * DW32];
__device__ uint32_t g_q[MTOT * DMODEL / 2];    // [b*16+h][l][32 u32]
__device__ uint32_t g_k[MTOT * DMODEL / 2];
__device__ uint16_t g_vt[MTOT * DMODEL];       // [b*16+h][hd][l] halves
__device__ uint32_t g_ctx[MTOT * DW32];        // [b*SEQ+l][512 u32]

__device__ __forceinline__ float ex2(float x) {
    float r;
    asm("ex2.approx.f32 %0, %1;" : "=f"(r) : "f"(x));
    return r;
}
__device__ __forceinline__ uint32_t smem_u32(const void* p) {
    uint32_t a;
    asm("{ .reg .u64 t; cvta.to.shared.u64 t, %1; cvt.u32.u64 %0, t; }" : "=r"(a) : "l"(p));
    return a;
}
__device__ __forceinline__ void cp16(uint32_t smem, const void* g) {
    asm volatile("cp.async.cg.shared.global [%0], [%1], 16;"
                 :: "r"(smem), "l"(__cvta_generic_to_global(g)));
}
__device__ __forceinline__ void mma_f16(float* d, const uint32_t* a, const uint32_t* b) {
    asm volatile(
        "mma.sync.aligned.m16n8k16.row.col.f32.f16.f16.f32 "
        "{%0,%1,%2,%3}, {%4,%5,%6,%7}, {%8,%9}, {%0,%1,%2,%3};\n"
        : "+f"(d[0]), "+f"(d[1]), "+f"(d[2]), "+f"(d[3])
        : "r"(a[0]), "r"(a[1]), "r"(a[2]), "r"(a[3]), "r"(b[0]), "r"(b[1]));
}
__device__ __forceinline__ void ldsm4(uint32_t& r0, uint32_t& r1, uint32_t& r2,
                                      uint32_t& r3, uint32_t a) {
    asm volatile("ldmatrix.sync.aligned.m8n8.x4.shared.b16 {%0,%1,%2,%3}, [%4];"
                 : "=r"(r0), "=r"(r1), "=r"(r2), "=r"(r3) : "r"(a));
}
__device__ __forceinline__ uint32_t h2bits(float a, float b) {
    __half2 h = __floats2half2_rn(a, b);
    return *reinterpret_cast<uint32_t*>(&h);
}
__device__ __forceinline__ uint16_t hbits(float a) {
    __half h = __float2half_rn(a);
    return *reinterpret_cast<uint16_t*>(&h);
}

// ---- mbarrier helpers (plain sm_100 PTX, no 'a' features) ----
#define MBAR_INIT(addr, cnt) \
    asm volatile("mbarrier.init.shared.b64 [%0], %1;" :: "r"(addr), "r"((uint32_t)(cnt)) : "memory")
#define MBAR_ARRIVE(addr) \
    asm volatile("mbarrier.arrive.shared.b64 _, [%0];" :: "r"(addr) : "memory")
#define CP_ARRIVE_NOINC(addr) \
    asm volatile("cp.async.mbarrier.arrive.noinc.shared::cta.b64 [%0];" :: "r"(addr) : "memory")

__device__ __forceinline__ void mbar_wait_parity(uint32_t mbar, uint32_t parity) {
    uint32_t done;
    asm volatile(
        "{\n\t.reg .pred p;\n\t"
        "mbarrier.try_wait.parity.shared.b64 p, [%1], %2;\n\t"
        "selp.b32 %0, 1, 0, p;\n\t}"
        : "=r"(done) : "r"(mbar), "r"(parity) : "memory");
    if (!done) {
        asm volatile(
            "{\n\t.reg .pred P1;\n\t"
            "W_%=:\n\t"
            "mbarrier.try_wait.parity.shared.b64 P1, [%0], %1;\n\t"
            "@P1 bra.uni D_%=;\n\t"
            "bra.uni W_%=;\n\t"
            "D_%=:\n\t}"
            :: "r"(mbar), "r"(parity) : "memory");
    }
}

// ---------------------------------------------------------------------------
// Fused fp16 round+pack of x and all 4 weights, 4-way MLP per thread.
// ---------------------------------------------------------------------------
#define X4 (MTOT * DMODEL / 4)
#define W4 (DMODEL * DMODEL / 4)
#define TOTAL4 (X4 + 4 * W4)          // 2097152 float4 elements
#define RP_CTAS 2048                  // 2048*256*4 = TOTAL4 exactly

__global__ __launch_bounds__(256) void round_pack(
    const float* __restrict__ x, const float* __restrict__ Wq,
    const float* __restrict__ Wk, const float* __restrict__ Wv,
    const float* __restrict__ Wo) {
    const int base = blockIdx.x * 1024 + threadIdx.x;   // 4 slots, stride 256

    const float* srcs[4];
    uint2* dsts[4];
    int lis[4];
#pragma unroll
    for (int u = 0; u < 4; u++) {
        const int idx = base + u * 256;
        if (idx < X4) {
            srcs[u] = x; dsts[u] = reinterpret_cast<uint2*>(g_xr); lis[u] = idx;
        } else {
            const int r = idx - X4;
            const int w = r >> 18;
            lis[u] = r & (W4 - 1);
            switch (w) {
                case 0: srcs[u] = Wq; dsts[u] = reinterpret_cast<uint2*>(g_wq); break;
                case 1: srcs[u] = Wk; dsts[u] = reinterpret_cast<uint2*>(g_wk); break;
                case 2: srcs[u] = Wv; dsts[u] = reinterpret_cast<uint2*>(g_wv); break;
                default: srcs[u] = Wo; dsts[u] = reinterpret_cast<uint2*>(g_wo); break;
            }
        }
    }

    float4 v[4];
#pragma unroll
    for (int u = 0; u < 4; u++)
        v[u] = reinterpret_cast<const float4*>(srcs[u])[lis[u]];

#pragma unroll
    for (int u = 0; u < 4; u++)
        dsts[u][lis[u]] = make_uint2(h2bits(v[u].x, v[u].y), h2bits(v[u].z, v[u].w));
}

// ---------------------------------------------------------------------------
// FP16 mma.sync GEMM with per-stage mbarrier producer/consumer pipeline
// (unchanged from R14/R15 — proven).
// ---------------------------------------------------------------------------
#define GSTR 36
#define GASTG (128 * GSTR)                   // A u32 per stage
#define GBSTG (64 * GSTR)                    // B u32 per stage
#define GMB   (2 * (GASTG + GBSTG))          // u32 offset of mbarriers
#define GSMEM_BYTES (GMB * 4 + 32)           // stages + 4 mbarriers = 55328 B
#define GNCHUNK 16
#define VT_STR 132                           // halves stride for V transpose

template <int MODE>
__global__ __launch_bounds__(128, 4) void gemm_mma(const uint32_t* __restrict__ A,
                                                   const uint32_t* __restrict__ B0,
                                                   const uint32_t* __restrict__ B1,
                                                   const uint32_t* __restrict__ B2,
                                                   float* __restrict__ Cf,
                                                   uint32_t* __restrict__ Cq,
                                                   uint32_t* __restrict__ Ck,
                                                   uint16_t* __restrict__ Cvt) {
    extern __shared__ uint32_t sm32[];
    const uint32_t as_a = smem_u32(sm32);
    const uint32_t bs_a = as_a + 2 * GASTG * 4;
    const uint32_t mb = as_a + GMB * 4;      // full0, full1, empty0, empty1

    const int tid = threadIdx.x;
    const int bm = blockIdx.y * 128;
    const int bnab = blockIdx.x * 64;

    const uint32_t* B = B0;
    int bn = bnab;
    if (MODE == 1) {
        if (bnab >= 2048)      B = B2;
        else if (bnab >= 1024) B = B1;
        bn = bnab & 1023;
    }

    const int wid = tid >> 5;
    const int lane = tid & 31;
    const int wm = (wid >> 1) * 64;
    const int wn = (wid & 1) * 32;
    const int gid = lane >> 2;
    const int tig = lane & 3;

    const int a_lrow = (lane & 7) + ((lane >> 3) & 1) * 8;
    const int a_lcol = (lane >> 4) * 4;
    const int b_lrow = (lane & 7) + (lane >> 4) * 8;
    const int b_lcol = ((lane >> 3) & 1) * 4;

    if (tid == 0) {
        MBAR_INIT(mb + 0, 128);
        MBAR_INIT(mb + 8, 128);
        MBAR_INIT(mb + 16, 128);
        MBAR_INIT(mb + 24, 128);
    }
    __syncthreads();

    auto issue_chunk = [&](int c, int buf) {
        const uint32_t ab = as_a + (uint32_t)buf * GASTG * 4;
        const uint32_t bb = bs_a + (uint32_t)buf * GBSTG * 4;
        const int k0 = c * 32;
#pragma unroll
        for (int u = 0; u < 8; u++) {
            const int idx = u * 128 + tid;
            const int r = idx >> 3;
            const int ch = idx & 7;
            cp16(ab + (uint32_t)(r * GSTR + ch * 4) * 4,
                 A + (size_t)(bm + r) * DW32 + k0 + ch * 4);
        }
#pragma unroll
        for (int u = 0; u < 4; u++) {
            const int idx = u * 128 + tid;
            const int r = idx >> 3;
            const int ch = idx & 7;
            cp16(bb + (uint32_t)(r * GSTR + ch * 4) * 4,
                 B + (size_t)(bn + r) * DW32 + k0 + ch * 4);
        }
    };

    float acc[4][4][4];
#pragma unroll
    for (int i = 0; i < 4; i++)
#pragma unroll
        for (int j = 0; j < 4; j++)
#pragma unroll
            for (int r = 0; r < 4; r++) acc[i][j][r] = 0.0f;

    issue_chunk(0, 0);
    CP_ARRIVE_NOINC(mb + 0);
    issue_chunk(1, 1);
    CP_ARRIVE_NOINC(mb + 8);

    for (int c = 0; c < GNCHUNK; c++) {
        const int s = c & 1;
        const uint32_t par = (uint32_t)((c >> 1) & 1);
        const uint32_t fullb = mb + (uint32_t)(s * 8);
        const uint32_t emptyb = mb + 16 + (uint32_t)(s * 8);

        mbar_wait_parity(fullb, par);

        const uint32_t aaddr = as_a + (uint32_t)s * GASTG * 4 +
                               (uint32_t)(((wm + a_lrow) * GSTR) + a_lcol) * 4;
        const uint32_t baddr = bs_a + (uint32_t)s * GBSTG * 4 +
                               (uint32_t)(((wn + b_lrow) * GSTR) + b_lcol) * 4;

        uint32_t af[2][4][4], bf[2][4][2];

        auto load_frags = [&](int kk, int d) {
#pragma unroll
            for (int mt = 0; mt < 4; mt++)
                ldsm4(af[d][mt][0], af[d][mt][1], af[d][mt][2], af[d][mt][3],
                      aaddr + (uint32_t)(mt * 16 * GSTR + kk) * 4);
#pragma unroll
            for (int u = 0; u < 2; u++)
                ldsm4(bf[d][2 * u][0], bf[d][2 * u][1],
                      bf[d][2 * u + 1][0], bf[d][2 * u + 1][1],
                      baddr + (uint32_t)(u * 16 * GSTR + kk) * 4);
        };

        load_frags(0, 0);
#pragma unroll
        for (int ks = 0; ks < 4; ks++) {
            const int cur = ks & 1;
            if (ks < 3) load_frags((ks + 1) * 8, cur ^ 1);
            if (ks == 2) MBAR_ARRIVE(emptyb);
#pragma unroll
            for (int mt = 0; mt < 4; mt++)
#pragma unroll
                for (int nt = 0; nt < 4; nt++)
                    mma_f16(acc[mt][nt], af[cur][mt], bf[cur][nt]);
        }

        if (c + 2 < GNCHUNK) {
            mbar_wait_parity(emptyb, par);
            issue_chunk(c + 2, s);
            CP_ARRIVE_NOINC(fullb);
        }
    }

    const bool is_q = (MODE == 1) && (bnab < 1024);
    const bool is_v = (MODE == 1) && (bnab >= 2048);

    if (is_v) {
        __syncthreads();
        uint16_t* svh = reinterpret_cast<uint16_t*>(sm32);
#pragma unroll
        for (int mt = 0; mt < 4; mt++) {
#pragma unroll
            for (int nt = 0; nt < 4; nt++) {
                const int col = wn + nt * 8 + 2 * tig;
#pragma unroll
                for (int half = 0; half < 2; half++) {
                    const int row = wm + mt * 16 + gid + 8 * half;
                    svh[(col)     * VT_STR + row] = hbits(acc[mt][nt][2 * half]);
                    svh[(col + 1) * VT_STR + row] = hbits(acc[mt][nt][2 * half + 1]);
                }
            }
        }
        __syncthreads();
        const int b = bm >> 11;
        const int bl = bm & (SEQ - 1);
        const int h = bn >> 6;
        const int bh = b * NHEAD + h;
        uint32_t* Cvt32 = reinterpret_cast<uint32_t*>(Cvt);
#pragma unroll
        for (int u = 0; u < 32; u++) {
            const int idx = u * 128 + tid;
            const int dd = idx >> 6;
            const int lc = idx & 63;
            const uint32_t val =
                *reinterpret_cast<const uint32_t*>(&svh[dd * VT_STR + 2 * lc]);
            Cvt32[(((size_t)bh * HDIM + dd) * SEQ + bl + 2 * lc) >> 1] = val;
        }
        return;
    }

#pragma unroll
    for (int mt = 0; mt < 4; mt++) {
        const int row0 = bm + wm + mt * 16 + gid;
#pragma unroll
        for (int nt = 0; nt < 4; nt++) {
            const int gcol = bn + wn + nt * 8 + 2 * tig;
#pragma unroll
            for (int half = 0; half < 2; half++) {
                const int row = row0 + 8 * half;
                float v0 = acc[mt][nt][2 * half];
                float v1 = acc[mt][nt][2 * half + 1];
                if (MODE == 0) {
                    *reinterpret_cast<float2*>(Cf + (size_t)row * DMODEL + gcol) =
                        make_float2(v0, v1);
                } else {
                    const int b = row >> 11;
                    const int l = row & (SEQ - 1);
                    const int h = gcol >> 6;
                    const int dd = gcol & (HDIM - 1);
                    const int bh = b * NHEAD + h;
                    if (is_q) { v0 *= CEXPF; v1 *= CEXPF; }
                    uint32_t* dst = (is_q ? Cq : Ck);
                    dst[((size_t)bh * SEQ + l) * 32 + (dd >> 1)] = h2bits(v0, v1);
                }
            }
        }
    }
}

// ---------------------------------------------------------------------------
// Flash attention, fp16 mma.sync m16n8k16, causal.
// NEW: 3-stage mbarrier producer/consumer pipeline (no __syncthreads, no
// commit/wait groups in main loop). Skipped diagonal warps arrive empty
// right after the full-wait so barrier counts stay exact.
// ---------------------------------------------------------------------------
#define FA_BK 64
#define FA_STR 36
#define FA_ST (64 * FA_STR)
#define FA_DATA (6 * FA_ST)                  // u32 of K+V stages
#define FA_SMEM_BYTES (FA_DATA * 4 + 48)     // + 6 mbarriers = 55344 B

__device__ __forceinline__ void fa_load_kv(uint32_t ks_a, uint32_t vs_a,
                                           const uint32_t* Kg, const uint16_t* Vtg,
                                           int k0, int stage, int tid) {
    const uint32_t ko = ks_a + (uint32_t)stage * (FA_ST * 4);
    const uint32_t vo = vs_a + (uint32_t)stage * (FA_ST * 4);
#pragma unroll
    for (int u = 0; u < 2; u++) {
        const int idx = u * 256 + tid;
        const int r = idx >> 3;
        const int ch = idx & 7;
        cp16(ko + (uint32_t)(r * FA_STR + ch * 4) * 4,
             Kg + (size_t)(k0 + r) * 32 + ch * 4);
        cp16(vo + (uint32_t)(r * FA_STR + ch * 4) * 4,
             Vtg + (size_t)r * SEQ + k0 + ch * 8);
    }
}

__global__ __launch_bounds__(256, 2) void flash_mma(const uint32_t* __restrict__ Q,
                                                    const uint32_t* __restrict__ K,
                                                    const uint16_t* __restrict__ Vt,
                                                    uint32_t* __restrict__ ctx) {
    extern __shared__ uint32_t fs32[];
    uint32_t* Ks = fs32;
    uint32_t* Vs = fs32 + 3 * FA_ST;

    const int tid = threadIdx.x;
    const int w = tid >> 5;
    const int lane = tid & 31;
    const int gid = lane >> 2;
    const int tig = lane & 3;
    const int bh = blockIdx.y;
    const int qb = (int)gridDim.x - 1 - (int)blockIdx.x;
    const int q0 = qb * 128;

    const int b_lrow = (lane & 7) + (lane >> 4) * 8;
    const int b_lcol = ((lane >> 3) & 1) * 4;

    const uint32_t* Qg = Q + ((size_t)bh * SEQ + q0) * 32;
    const uint32_t* Kg = K + (size_t)bh * SEQ * 32;
    const uint16_t* Vtg = Vt + (size_t)bh * HDIM * SEQ;

    const uint32_t ks_a = smem_u32(Ks);
    const uint32_t vs_a = smem_u32(Vs);
    const uint32_t fmb = ks_a + FA_DATA * 4;     // full0..2, empty0..2 (8B each)

    const int nkb = 2 * qb + 2;
    const int rq = 16 * w + gid;

    if (tid == 0) {
#pragma unroll
        for (int s = 0; s < 3; s++) {
            MBAR_INIT(fmb + s * 8, 256);         // full[s]
            MBAR_INIT(fmb + 24 + s * 8, 256);    // empty[s]
        }
    }
    __syncthreads();

    // prologue: 2 stages in flight
    fa_load_kv(ks_a, vs_a, Kg, Vtg, 0, 0, tid);
    CP_ARRIVE_NOINC(fmb + 0);
    if (nkb > 1) {
        fa_load_kv(ks_a, vs_a, Kg, Vtg, FA_BK, 1, tid);
        CP_ARRIVE_NOINC(fmb + 8);
    }

    uint32_t qa_all[4][4];
#pragma unroll
    for (int g = 0; g < 4; g++) {
        qa_all[g][0] = Qg[(size_t)rq * 32 + 8 * g + tig];
        qa_all[g][1] = Qg[(size_t)(rq + 8) * 32 + 8 * g + tig];
        qa_all[g][2] = Qg[(size_t)rq * 32 + 8 * g + tig + 4];
        qa_all[g][3] = Qg[(size_t)(rq + 8) * 32 + 8 * g + tig + 4];
    }

    float o[8][4];
#pragma unroll
    for (int nt = 0; nt < 8; nt++)
#pragma unroll
        for (int e = 0; e < 4; e++) o[nt][e] = 0.0f;
    float m0 = -1e30f, m1 = -1e30f, l0 = 0.0f, l1 = 0.0f;

    for (int kb = 0; kb < nkb; kb++) {
        const int s = kb % 3;
        const uint32_t fpar = (uint32_t)((kb / 3) & 1);
        const uint32_t fullb = fmb + (uint32_t)(s * 8);
        const uint32_t emptyb = fmb + 24 + (uint32_t)(s * 8);

        mbar_wait_parity(fullb, fpar);

        // issue kb+2 into stage s2 (first wait for its previous consumption)
        if (kb + 2 < nkb) {
            const int s2 = (kb + 2) % 3;
            if (kb >= 1)
                mbar_wait_parity(fmb + 24 + (uint32_t)(s2 * 8),
                                 (uint32_t)(((kb - 1) / 3) & 1));
            fa_load_kv(ks_a, vs_a, Kg, Vtg, (kb + 2) * FA_BK, s2, tid);
            CP_ARRIVE_NOINC(fmb + (uint32_t)(s2 * 8));
        }

        const int k0 = kb * FA_BK;
        if (k0 > q0 + 16 * w + 15) {      // fully-masked warp-block: consume & go
            MBAR_ARRIVE(emptyb);
            continue;
        }

        const uint32_t kaddr = ks_a + (uint32_t)s * FA_ST * 4 +
                               (uint32_t)(b_lrow * FA_STR + b_lcol) * 4;
        const uint32_t vaddr = vs_a + (uint32_t)s * FA_ST * 4 +
                               (uint32_t)(b_lrow * FA_STR + b_lcol) * 4;

        float c[8][4];
#pragma unroll
        for (int nt = 0; nt < 8; nt++)
#pragma unroll
            for (int e = 0; e < 4; e++) c[nt][e] = 0.0f;

#pragma unroll
        for (int g = 0; g < 4; g++) {
            uint32_t kf[8][2];
#pragma unroll
            for (int u = 0; u < 4; u++)
                ldsm4(kf[2 * u][0], kf[2 * u][1], kf[2 * u + 1][0], kf[2 * u + 1][1],
                      kaddr + (uint32_t)(u * 16 * FA_STR + 8 * g) * 4);
#pragma unroll
            for (int nt = 0; nt < 8; nt++) mma_f16(c[nt], qa_all[g], kf[nt]);
        }

        if (k0 + 63 > q0 + 16 * w) {
            const int r0g = q0 + rq;
#pragma unroll
            for (int nt = 0; nt < 8; nt++) {
                const int cb = k0 + 8 * nt + 2 * tig;
                if (cb > r0g) c[nt][0] = -1e30f;
                if (cb + 1 > r0g) c[nt][1] = -1e30f;
                if (cb > r0g + 8) c[nt][2] = -1e30f;
                if (cb + 1 > r0g + 8) c[nt][3] = -1e30f;
            }
        }

        float mx0 = -1e30f, mx1 = -1e30f;
#pragma unroll
        for (int nt = 0; nt < 8; nt++) {
            mx0 = fmaxf(mx0, fmaxf(c[nt][0], c[nt][1]));
            mx1 = fmaxf(mx1, fmaxf(c[nt][2], c[nt][3]));
        }
        mx0 = fmaxf(mx0, __shfl_xor_sync(0xffffffffu, mx0, 1));
        mx0 = fmaxf(mx0, __shfl_xor_sync(0xffffffffu, mx0, 2));
        mx1 = fmaxf(mx1, __shfl_xor_sync(0xffffffffu, mx1, 1));
        mx1 = fmaxf(mx1, __shfl_xor_sync(0xffffffffu, mx1, 2));

        const float mn0 = fmaxf(fmaxf(m0, mx0), -1000.0f);
        const float mn1 = fmaxf(fmaxf(m1, mx1), -1000.0f);
        const float corr0 = ex2(m0 - mn0);
        const float corr1 = ex2(m1 - mn1);

        float rs0 = 0.0f, rs1 = 0.0f;
        uint32_t pw[8][2];
#pragma unroll
        for (int nt = 0; nt < 8; nt++) {
            const float p0 = ex2(c[nt][0] - mn0);
            const float p1 = ex2(c[nt][1] - mn0);
            const float p2 = ex2(c[nt][2] - mn1);
            const float p3 = ex2(c[nt][3] - mn1);
            rs0 += p0 + p1;
            rs1 += p2 + p3;
            pw[nt][0] = h2bits(p0, p1);
            pw[nt][1] = h2bits(p2, p3);
        }

#pragma unroll
        for (int nt = 0; nt < 8; nt++) {
            o[nt][0] *= corr0;
            o[nt][1] *= corr0;
            o[nt][2] *= corr1;
            o[nt][3] *= corr1;
        }

#pragma unroll
        for (int j = 0; j < 4; j++) {
            uint32_t pa[4] = {pw[2 * j][0], pw[2 * j][1],
                              pw[2 * j + 1][0], pw[2 * j + 1][1]};
            uint32_t vf[8][2];
#pragma unroll
            for (int u = 0; u < 4; u++)
                ldsm4(vf[2 * u][0], vf[2 * u][1], vf[2 * u + 1][0], vf[2 * u + 1][1],
                      vaddr + (uint32_t)(u * 16 * FA_STR + 8 * j) * 4);
#pragma unroll
            for (int nt = 0; nt < 8; nt++) mma_f16(o[nt], pa, vf[nt]);
        }

        MBAR_ARRIVE(emptyb);     // done reading stage s (K and V)

        rs0 += __shfl_xor_sync(0xffffffffu, rs0, 1);
        rs0 += __shfl_xor_sync(0xffffffffu, rs0, 2);
        rs1 += __shfl_xor_sync(0xffffffffu, rs1, 1);
        rs1 += __shfl_xor_sync(0xffffffffu, rs1, 2);
        l0 = l0 * corr0 + rs0;
        l1 = l1 * corr1 + rs1;
        m0 = mn0;
        m1 = mn1;
    }

    const float inv0 = 1.0f / l0;
    const float inv1 = 1.0f / l1;
    const int b = bh >> 4;
    const int h = bh & 15;
    const int r0 = q0 + rq;
#pragma unroll
    for (int nt = 0; nt < 8; nt++) {
        const int ci = h * 32 + 4 * nt + tig;
        ctx[((size_t)(b * SEQ + r0)) * DW32 + ci] = h2bits(o[nt][0] * inv0, o[nt][1] * inv0);
        ctx[((size_t)(b * SEQ + r0 + 8)) * DW32 + ci] = h2bits(o[nt][2] * inv1, o[nt][3] * inv1);
    }
}

// ---------------------------------------------------------------------------
// Launch
// ---------------------------------------------------------------------------
template <typename T>
static T* sym_addr(const void* symbol) {
    void* p = nullptr;
    cudaGetSymbolAddress(&p, symbol);
    return reinterpret_cast<T*>(p);
}

extern "C" void kernel_launch(void* const* d_in, const int* in_sizes, int n_in,
                              void* d_out, int out_size) {
    const float* x  = (const float*)d_in[0];
    const float* Wq = (const float*)d_in[1];
    const float* Wk = (const float*)d_in[2];
    const float* Wv = (const float*)d_in[3];
    const float* Wo = (const float*)d_in[4];
    float* out = (float*)d_out;

    uint32_t* xr = sym_addr<uint32_t>(g_xr);
    uint32_t* wq = sym_addr<uint32_t>(g_wq);
    uint32_t* wk = sym_addr<uint32_t>(g_wk);
    uint32_t* wv = sym_addr<uint32_t>(g_wv);
    uint32_t* wo = sym_addr<uint32_t>(g_wo);
    uint32_t* q  = sym_addr<uint32_t>(g_q);
    uint32_t* k  = sym_addr<uint32_t>(g_k);
    uint16_t* vt = sym_addr<uint16_t>(g_vt);
    uint32_t* ctx = sym_addr<uint32_t>(g_ctx);

    cudaFuncSetAttribute(gemm_mma<1>, cudaFuncAttributeMaxDynamicSharedMemorySize, GSMEM_BYTES);
    cudaFuncSetAttribute(gemm_mma<0>, cudaFuncAttributeMaxDynamicSharedMemorySize, GSMEM_BYTES);
    cudaFuncSetAttribute(flash_mma, cudaFuncAttributeMaxDynamicSharedMemorySize, FA_SMEM_BYTES);

    round_pack<<<RP_CTAS, 256>>>(x, Wq, Wk, Wv, Wo);

    dim3 gqkv(3 * DMODEL / 64, MTOT / 128);    // (48, 32) = 1536 CTAs
    gemm_mma<1><<<gqkv, 128, GSMEM_BYTES>>>(xr, wq, wk, wv, nullptr, q, k, vt);

    dim3 ga(SEQ / 128, BATCH * NHEAD);         // (16, 32)
    flash_mma<<<ga, 256, FA_SMEM_BYTES>>>(q, k, vt, ctx);

    dim3 go(DMODEL / 64, MTOT / 128);          // (16, 32) = 512 CTAs
    gemm_mma<0><<<go, 128, GSMEM_BYTES>>>(ctx, wo, nullptr, nullptr, out, nullptr, nullptr, nullptr);
}